// round 5
// baseline (speedup 1.0000x reference)
#include <cuda_runtime.h>
#include <cstdint>

#define N_NODES 20000
#define IN_DIM 256
#define HID 128
#define OUT_DIM 64
#define N_LAYERS 4
#define N_PATHS 8
#define PATH_LEN 8
#define N_TYPES 2

// -------- scratch (no allocations allowed; device globals) --------
__device__ float g_in_feats[N_NODES * HID];
__device__ float g_bufA[N_NODES * HID];
__device__ float g_bufB[N_NODES * HID];
__device__ float g_fout[N_NODES * N_TYPES * HID];
__device__ float g_wres[N_TYPES * PATH_LEN * HID];   // type+mean-resolved weights

__device__ __forceinline__ float* buf_ptr(int s) {
    return s == 0 ? g_in_feats : (s == 1 ? g_bufA : g_bufB);
}

__device__ __forceinline__ uint32_t f2tf32(float f) {
    uint32_t u;
    asm("cvt.rna.tf32.f32 %0, %1;" : "=r"(u) : "f"(f));
    return u;
}

__device__ __forceinline__ void mma_tf32(
    float& d0, float& d1, float& d2, float& d3,
    uint32_t a0, uint32_t a1, uint32_t a2, uint32_t a3,
    uint32_t b0, uint32_t b1)
{
    asm volatile(
        "mma.sync.aligned.m16n8k8.row.col.f32.tf32.tf32.f32 "
        "{%0,%1,%2,%3}, {%4,%5,%6,%7}, {%8,%9}, {%0,%1,%2,%3};\n"
        : "+f"(d0), "+f"(d1), "+f"(d2), "+f"(d3)
        : "r"(a0), "r"(a1), "r"(a2), "r"(a3), "r"(b0), "r"(b1));
}

// ============================================================================
// Prep: wres[t][l][h] = pw[t][l][h] / count[t]   (2048 elements)
// ============================================================================
__global__ void resolve_w_kernel(const float* __restrict__ pw,
                                 const int* __restrict__ ptypes)
{
    int i = blockIdx.x * blockDim.x + threadIdx.x;
    if (i >= N_TYPES * PATH_LEN * HID) return;
    int t = i / (PATH_LEN * HID);
    int cnt = 0;
#pragma unroll
    for (int p = 0; p < N_PATHS; p++) cnt += (__ldg(ptypes + p) == t);
    float inv = cnt > 0 ? 1.0f / (float)cnt : 0.0f;
    g_wres[i] = __ldg(pw + i) * inv;
}

// ============================================================================
// TF32 tensor-core GEMM:  C[M, BN] = EPI( A[M, KDIM] @ W[BN, KDIM]^T )
//   EPI==0: relu(acc + bias[n])
//   EPI==1: 0.8*relu(acc) + 0.1*pre + 0.1*inf
// Block: 128 x BN tile, 256 threads (8 warps: 4 M x 2 N), warp 32 x (BN/2).
// Register-prefetch of next k-stage overlaps LDG with MMA.
// ============================================================================
template <int KDIM, int BN, int EPI>
__device__ __forceinline__ void gemm_tc_body(
    const float* __restrict__ A, const float* __restrict__ W,
    const float* __restrict__ bias, const float* __restrict__ pre,
    const float* __restrict__ inf, float* __restrict__ C)
{
    constexpr int BM = 128, BK = 32, LDS_ = 36;
    constexpr int NT = BN / 16;
    constexpr int NB = (BN == 128) ? 4 : 2;   // B float4s per thread per stage
    __shared__ uint32_t As[BM * LDS_];
    __shared__ uint32_t Bs[BN * LDS_];

    const int tid    = threadIdx.x;
    const int lane   = tid & 31;
    const int warp   = tid >> 5;
    const int warp_m = warp & 3;
    const int warp_n = warp >> 2;
    const int gid    = lane >> 2;
    const int tig    = lane & 3;
    const int m0     = blockIdx.x * BM;

    float acc[2][NT][4];
#pragma unroll
    for (int mt = 0; mt < 2; mt++)
#pragma unroll
        for (int nt = 0; nt < NT; nt++)
#pragma unroll
            for (int r = 0; r < 4; r++) acc[mt][nt][r] = 0.f;

    // A loader: row = tid>>1, 16 consecutive k at (tid&1)*16
    const int  a_row  = tid >> 1;
    const int  a_cb   = (tid & 1) << 4;
    const bool a_ok   = (m0 + a_row) < N_NODES;
    const float* Aptr = A + (size_t)(m0 + a_row) * KDIM + a_cb;
    // B loader mapping
    const int  b_row  = (BN == 128) ? (tid >> 1) : (tid >> 2);
    const int  b_cb   = (BN == 128) ? ((tid & 1) << 4) : ((tid & 3) << 3);
    const float* Wptr = W + (size_t)b_row * KDIM + b_cb;

    float4 ra[4], rb[NB];
    // prologue loads for k0 = 0
#pragma unroll
    for (int i = 0; i < 4; i++)
        ra[i] = a_ok ? *(const float4*)(Aptr + i * 4)
                     : make_float4(0.f, 0.f, 0.f, 0.f);
#pragma unroll
    for (int i = 0; i < NB; i++)
        rb[i] = *(const float4*)(Wptr + i * 4);

    for (int k0 = 0; k0 < KDIM; k0 += BK) {
        // ---- convert + store current stage ----
        {
            uint32_t* dst = As + a_row * LDS_ + a_cb;
#pragma unroll
            for (int i = 0; i < 4; i++) {
                uint4 u;
                u.x = f2tf32(ra[i].x); u.y = f2tf32(ra[i].y);
                u.z = f2tf32(ra[i].z); u.w = f2tf32(ra[i].w);
                *(uint4*)(dst + i * 4) = u;
            }
            uint32_t* dstb = Bs + b_row * LDS_ + b_cb;
#pragma unroll
            for (int i = 0; i < NB; i++) {
                uint4 u;
                u.x = f2tf32(rb[i].x); u.y = f2tf32(rb[i].y);
                u.z = f2tf32(rb[i].z); u.w = f2tf32(rb[i].w);
                *(uint4*)(dstb + i * 4) = u;
            }
        }
        __syncthreads();

        // ---- prefetch next stage into registers ----
        if (k0 + BK < KDIM) {
#pragma unroll
            for (int i = 0; i < 4; i++)
                ra[i] = a_ok ? *(const float4*)(Aptr + k0 + BK + i * 4)
                             : make_float4(0.f, 0.f, 0.f, 0.f);
#pragma unroll
            for (int i = 0; i < NB; i++)
                rb[i] = *(const float4*)(Wptr + k0 + BK + i * 4);
        }

        // ---- MMA over current stage ----
#pragma unroll
        for (int kk = 0; kk < BK / 8; kk++) {
            const int kb = kk * 8;
            uint32_t a[2][4];
#pragma unroll
            for (int mt = 0; mt < 2; mt++) {
                int r = warp_m * 32 + mt * 16 + gid;
                a[mt][0] = As[r * LDS_ + kb + tig];
                a[mt][1] = As[(r + 8) * LDS_ + kb + tig];
                a[mt][2] = As[r * LDS_ + kb + tig + 4];
                a[mt][3] = As[(r + 8) * LDS_ + kb + tig + 4];
            }
            uint32_t b[NT][2];
#pragma unroll
            for (int nt = 0; nt < NT; nt++) {
                int c = warp_n * (NT * 8) + nt * 8 + gid;
                b[nt][0] = Bs[c * LDS_ + kb + tig];
                b[nt][1] = Bs[c * LDS_ + kb + tig + 4];
            }
#pragma unroll
            for (int mt = 0; mt < 2; mt++)
#pragma unroll
                for (int nt = 0; nt < NT; nt++)
                    mma_tf32(acc[mt][nt][0], acc[mt][nt][1],
                             acc[mt][nt][2], acc[mt][nt][3],
                             a[mt][0], a[mt][1], a[mt][2], a[mt][3],
                             b[nt][0], b[nt][1]);
        }
        __syncthreads();
    }

    // ---- epilogue ----
#pragma unroll
    for (int mt = 0; mt < 2; mt++) {
#pragma unroll
        for (int half = 0; half < 2; half++) {
            int row = m0 + warp_m * 32 + mt * 16 + half * 8 + gid;
            if (row >= N_NODES) continue;
#pragma unroll
            for (int nt = 0; nt < NT; nt++) {
                int col = warp_n * (NT * 8) + nt * 8 + 2 * tig;
                float v0 = acc[mt][nt][half * 2 + 0];
                float v1 = acc[mt][nt][half * 2 + 1];
                size_t off = (size_t)row * BN + col;
                if constexpr (EPI == 0) {
                    v0 = fmaxf(v0 + bias[col], 0.f);
                    v1 = fmaxf(v1 + bias[col + 1], 0.f);
                } else {
                    float2 p2 = *(const float2*)(pre + off);
                    float2 f2 = *(const float2*)(inf + off);
                    v0 = 0.8f * fmaxf(v0, 0.f) + 0.1f * p2.x + 0.1f * f2.x;
                    v1 = 0.8f * fmaxf(v1, 0.f) + 0.1f * p2.y + 0.1f * f2.y;
                }
                *(float2*)(C + off) = make_float2(v0, v1);
            }
        }
    }
}

__global__ void __launch_bounds__(256)
fc_in_kernel(const float* __restrict__ x, const float* __restrict__ w,
             const float* __restrict__ b)
{
    gemm_tc_body<IN_DIM, HID, 0>(x, w, b, nullptr, nullptr, g_in_feats);
}

__global__ void __launch_bounds__(256)
layer_gemm_kernel(const float* __restrict__ w, int pre_sel, int out_sel)
{
    gemm_tc_body<N_TYPES * HID, HID, 1>(g_fout, w, nullptr,
                                        buf_ptr(pre_sel), g_in_feats,
                                        buf_ptr(out_sel));
}

__global__ void __launch_bounds__(256)
fc_out_kernel(const float* __restrict__ w, const float* __restrict__ b,
              float* __restrict__ out, int feats_sel)
{
    gemm_tc_body<HID, OUT_DIM, 0>(buf_ptr(feats_sel), w, b, nullptr, nullptr, out);
}

// ============================================================================
// Gather (select-free):
//   indices permuted by path type in smem (type-0 paths first), pre-scaled
//   to float4 element offsets; weights pre-resolved+mean-scaled in g_wres.
//   Two runtime-bounded loops accumulate acc0 / acc1 with zero selects.
// 1 warp per node, 8 nodes per 256-thread block.
// ============================================================================
__global__ void __launch_bounds__(256)
gather_kernel(const int* __restrict__ paths, const int* __restrict__ ptypes,
              int feats_sel)
{
    const float4* __restrict__ feats4 = (const float4*)buf_ptr(feats_sel);
    const float4* __restrict__ wres4  = (const float4*)g_wres;

    __shared__ int off_s[8][N_PATHS * PATH_LEN];   // type-grouped, pre-scaled
    __shared__ int types_s[N_PATHS];

    const int tid  = threadIdx.x;
    const int slot = tid >> 5;
    const int lane = tid & 31;
    const int n    = blockIdx.x * 8 + slot;

    if (tid < N_PATHS) types_s[tid] = ptypes[tid];
    __syncthreads();

    unsigned tmask = 0;
#pragma unroll
    for (int p = 0; p < N_PATHS; p++)
        tmask |= (types_s[p] ? 1u : 0u) << p;
    const int c0 = N_PATHS - __popc(tmask);

    // fill permuted, pre-scaled offsets: 512 entries, 2 per thread
    {
        int i  = tid * 2;
        int sl = i >> 6;
        int r  = i & 63;
        int p  = r >> 3, l = r & 7;
        int nn = blockIdx.x * 8 + sl;
        int2 v = *(const int2*)(paths + (size_t)p * (N_NODES * PATH_LEN)
                                + (size_t)nn * PATH_LEN + l);
        unsigned below = (1u << p) - 1u;
        int pos = (tmask >> p) & 1
                ? c0 + __popc(tmask & below)
                : __popc(~tmask & below & 0xFFu);
        off_s[sl][pos * PATH_LEN + l]     = v.x * (HID / 4);
        off_s[sl][pos * PATH_LEN + l + 1] = v.y * (HID / 4);
    }
    __syncthreads();

    const float4* fb = feats4 + lane;
    const int* orow = off_s[slot];

    float4 acc0 = make_float4(0.f, 0.f, 0.f, 0.f);
    {
        float4 w[PATH_LEN];
#pragma unroll
        for (int l = 0; l < PATH_LEN; l++)
            w[l] = __ldg(wres4 + (size_t)l * (HID / 4) + lane);
        for (int pp = 0; pp < c0; pp++) {
            int4 o0 = *(const int4*)(orow + pp * PATH_LEN);
            int4 o1 = *(const int4*)(orow + pp * PATH_LEN + 4);
            float4 f0 = __ldg(fb + o0.x), f1 = __ldg(fb + o0.y);
            float4 f2 = __ldg(fb + o0.z), f3 = __ldg(fb + o0.w);
            float4 f4 = __ldg(fb + o1.x), f5 = __ldg(fb + o1.y);
            float4 f6 = __ldg(fb + o1.z), f7 = __ldg(fb + o1.w);
#define ACC(F, L) \
            acc0.x = fmaf(F.x, w[L].x, acc0.x); \
            acc0.y = fmaf(F.y, w[L].y, acc0.y); \
            acc0.z = fmaf(F.z, w[L].z, acc0.z); \
            acc0.w = fmaf(F.w, w[L].w, acc0.w);
            ACC(f0, 0) ACC(f1, 1) ACC(f2, 2) ACC(f3, 3)
            ACC(f4, 4) ACC(f5, 5) ACC(f6, 6) ACC(f7, 7)
#undef ACC
        }
    }
    float4 acc1 = make_float4(0.f, 0.f, 0.f, 0.f);
    {
        float4 w[PATH_LEN];
#pragma unroll
        for (int l = 0; l < PATH_LEN; l++)
            w[l] = __ldg(wres4 + (size_t)(PATH_LEN + l) * (HID / 4) + lane);
        for (int pp = c0; pp < N_PATHS; pp++) {
            int4 o0 = *(const int4*)(orow + pp * PATH_LEN);
            int4 o1 = *(const int4*)(orow + pp * PATH_LEN + 4);
            float4 f0 = __ldg(fb + o0.x), f1 = __ldg(fb + o0.y);
            float4 f2 = __ldg(fb + o0.z), f3 = __ldg(fb + o0.w);
            float4 f4 = __ldg(fb + o1.x), f5 = __ldg(fb + o1.y);
            float4 f6 = __ldg(fb + o1.z), f7 = __ldg(fb + o1.w);
#define ACC(F, L) \
            acc1.x = fmaf(F.x, w[L].x, acc1.x); \
            acc1.y = fmaf(F.y, w[L].y, acc1.y); \
            acc1.z = fmaf(F.z, w[L].z, acc1.z); \
            acc1.w = fmaf(F.w, w[L].w, acc1.w);
            ACC(f0, 0) ACC(f1, 1) ACC(f2, 2) ACC(f3, 3)
            ACC(f4, 4) ACC(f5, 5) ACC(f6, 6) ACC(f7, 7)
#undef ACC
        }
    }

    float4* fo4 = (float4*)(g_fout + (size_t)n * (N_TYPES * HID));
    fo4[lane]           = acc0;   // mean already folded into weights
    fo4[HID / 4 + lane] = acc1;
}

// ============================================================================
extern "C" void kernel_launch(void* const* d_in, const int* in_sizes, int n_in,
                              void* d_out, int out_size)
{
    const float* input_x    = (const float*)d_in[0];
    const int*   paths      = (const int*)d_in[1];
    const int*   ptypes     = (const int*)d_in[2];
    const float* fc_in_w    = (const float*)d_in[3];
    const float* fc_in_b    = (const float*)d_in[4];
    const float* fc_out_w   = (const float*)d_in[5];
    const float* fc_out_b   = (const float*)d_in[6];
    const float* layer_fc_w = (const float*)d_in[7];
    const float* path_w     = (const float*)d_in[8];
    float* out = (float*)d_out;

    const dim3 blk(256);
    const dim3 ggrd((N_NODES + 127) / 128);

    fc_in_kernel<<<ggrd, blk>>>(input_x, fc_in_w, fc_in_b);

    int cur = 0;  // feats = g_in_feats
    for (int i = 0; i < N_LAYERS; i++) {
        resolve_w_kernel<<<(N_TYPES * PATH_LEN * HID + 255) / 256, blk>>>(
            path_w + (size_t)i * N_TYPES * PATH_LEN * HID, ptypes);
        gather_kernel<<<N_NODES / 8, blk>>>(paths, ptypes, cur);
        int nxt = (cur == 1) ? 2 : 1;
        layer_gemm_kernel<<<ggrd, blk>>>(
            layer_fc_w + (size_t)i * HID * (N_TYPES * HID), cur, nxt);
        cur = nxt;
    }

    fc_out_kernel<<<ggrd, blk>>>(fc_out_w, fc_out_b, out, cur);
}

// round 6
// speedup vs baseline: 1.0763x; 1.0763x over previous
#include <cuda_runtime.h>
#include <cstdint>

#define N_NODES 20000
#define IN_DIM 256
#define HID 128
#define OUT_DIM 64
#define N_LAYERS 4
#define N_PATHS 8
#define PATH_LEN 8
#define N_TYPES 2

// -------- scratch (no allocations allowed; device globals) --------
__device__ float g_in_feats[N_NODES * HID];
__device__ float g_bufA[N_NODES * HID];
__device__ float g_bufB[N_NODES * HID];
__device__ float g_fout[N_NODES * N_TYPES * HID];
__device__ float g_wres[N_TYPES * PATH_LEN * HID];   // type+mean-resolved weights

__device__ __forceinline__ float* buf_ptr(int s) {
    return s == 0 ? g_in_feats : (s == 1 ? g_bufA : g_bufB);
}

__device__ __forceinline__ uint32_t f2tf32(float f) {
    uint32_t u;
    asm("cvt.rna.tf32.f32 %0, %1;" : "=r"(u) : "f"(f));
    return u;
}

__device__ __forceinline__ void mma_tf32(
    float& d0, float& d1, float& d2, float& d3,
    uint32_t a0, uint32_t a1, uint32_t a2, uint32_t a3,
    uint32_t b0, uint32_t b1)
{
    asm volatile(
        "mma.sync.aligned.m16n8k8.row.col.f32.tf32.tf32.f32 "
        "{%0,%1,%2,%3}, {%4,%5,%6,%7}, {%8,%9}, {%0,%1,%2,%3};\n"
        : "+f"(d0), "+f"(d1), "+f"(d2), "+f"(d3)
        : "r"(a0), "r"(a1), "r"(a2), "r"(a3), "r"(b0), "r"(b1));
}

// ============================================================================
// Prep: wres[t][l][h] = pw[t][l][h] / count[t]   (2048 elements)
// ============================================================================
__global__ void resolve_w_kernel(const float* __restrict__ pw,
                                 const int* __restrict__ ptypes)
{
    int i = blockIdx.x * blockDim.x + threadIdx.x;
    if (i >= N_TYPES * PATH_LEN * HID) return;
    int t = i / (PATH_LEN * HID);
    int cnt = 0;
#pragma unroll
    for (int p = 0; p < N_PATHS; p++) cnt += (__ldg(ptypes + p) == t);
    float inv = cnt > 0 ? 1.0f / (float)cnt : 0.0f;
    g_wres[i] = __ldg(pw + i) * inv;
}

// ============================================================================
// TF32 tensor-core GEMM:  C[M, BN] = EPI( A[M, KDIM] @ W[BN, KDIM]^T )
//   EPI==0: relu(acc + bias[n])
//   EPI==1: 0.8*relu(acc) + 0.1*pre + 0.1*inf
// Block tile 64 x BN, 256 threads (4 warps M x 2 warps N), warp 16 x (BN/2).
// grid = 313 -> ~2 CTAs/SM so one CTA's staging overlaps the other's MMA.
// ============================================================================
template <int KDIM, int BN, int EPI>
__device__ __forceinline__ void gemm_tc_body(
    const float* __restrict__ A, const float* __restrict__ W,
    const float* __restrict__ bias, const float* __restrict__ pre,
    const float* __restrict__ inf, float* __restrict__ C)
{
    constexpr int BM = 64, BK = 32, LDS_ = 36;
    constexpr int NT = BN / 16;                  // 8 for BN=128, 4 for BN=64
    constexpr int NBA = 2;                       // A float4s / thread / stage
    constexpr int NBB = (BN == 128) ? 4 : 2;     // B float4s / thread / stage
    __shared__ uint32_t As[BM * LDS_];
    __shared__ uint32_t Bs[BN * LDS_];

    const int tid    = threadIdx.x;
    const int lane   = tid & 31;
    const int warp   = tid >> 5;
    const int warp_m = warp & 3;          // 16 rows each
    const int warp_n = warp >> 2;         // NT*8 cols each
    const int gid    = lane >> 2;
    const int tig    = lane & 3;
    const int m0     = blockIdx.x * BM;

    float acc[NT][4];
#pragma unroll
    for (int nt = 0; nt < NT; nt++)
#pragma unroll
        for (int r = 0; r < 4; r++) acc[nt][r] = 0.f;

    // A loader: row = tid>>2 (0..63), 8 k at (tid&3)*8
    const int  a_row  = tid >> 2;
    const int  a_cb   = (tid & 3) << 3;
    const bool a_ok   = (m0 + a_row) < N_NODES;
    const float* Aptr = A + (size_t)(m0 + a_row) * KDIM + a_cb;
    // B loader
    const int  b_row  = (BN == 128) ? (tid >> 1) : (tid >> 2);
    const int  b_cb   = (BN == 128) ? ((tid & 1) << 4) : ((tid & 3) << 3);
    const float* Wptr = W + (size_t)b_row * KDIM + b_cb;

    for (int k0 = 0; k0 < KDIM; k0 += BK) {
        // ---- stage A ----
        {
            uint32_t* dst = As + a_row * LDS_ + a_cb;
#pragma unroll
            for (int i = 0; i < NBA; i++) {
                float4 v = make_float4(0.f, 0.f, 0.f, 0.f);
                if (a_ok) v = *(const float4*)(Aptr + k0 + i * 4);
                uint4 u;
                u.x = f2tf32(v.x); u.y = f2tf32(v.y);
                u.z = f2tf32(v.z); u.w = f2tf32(v.w);
                *(uint4*)(dst + i * 4) = u;
            }
        }
        // ---- stage B ----
        {
            uint32_t* dst = Bs + b_row * LDS_ + b_cb;
#pragma unroll
            for (int i = 0; i < NBB; i++) {
                float4 v = *(const float4*)(Wptr + k0 + i * 4);
                uint4 u;
                u.x = f2tf32(v.x); u.y = f2tf32(v.y);
                u.z = f2tf32(v.z); u.w = f2tf32(v.w);
                *(uint4*)(dst + i * 4) = u;
            }
        }
        __syncthreads();

#pragma unroll
        for (int kk = 0; kk < BK / 8; kk++) {
            const int kb = kk * 8;
            uint32_t a[4];
            {
                int r = warp_m * 16 + gid;
                a[0] = As[r * LDS_ + kb + tig];
                a[1] = As[(r + 8) * LDS_ + kb + tig];
                a[2] = As[r * LDS_ + kb + tig + 4];
                a[3] = As[(r + 8) * LDS_ + kb + tig + 4];
            }
            uint32_t b[NT][2];
#pragma unroll
            for (int nt = 0; nt < NT; nt++) {
                int c = warp_n * (NT * 8) + nt * 8 + gid;
                b[nt][0] = Bs[c * LDS_ + kb + tig];
                b[nt][1] = Bs[c * LDS_ + kb + tig + 4];
            }
#pragma unroll
            for (int nt = 0; nt < NT; nt++)
                mma_tf32(acc[nt][0], acc[nt][1], acc[nt][2], acc[nt][3],
                         a[0], a[1], a[2], a[3], b[nt][0], b[nt][1]);
        }
        __syncthreads();
    }

    // ---- epilogue ----
#pragma unroll
    for (int half = 0; half < 2; half++) {
        int row = m0 + warp_m * 16 + half * 8 + gid;
        if (row >= N_NODES) continue;
#pragma unroll
        for (int nt = 0; nt < NT; nt++) {
            int col = warp_n * (NT * 8) + nt * 8 + 2 * tig;
            float v0 = acc[nt][half * 2 + 0];
            float v1 = acc[nt][half * 2 + 1];
            size_t off = (size_t)row * BN + col;
            if constexpr (EPI == 0) {
                v0 = fmaxf(v0 + bias[col], 0.f);
                v1 = fmaxf(v1 + bias[col + 1], 0.f);
            } else {
                float2 p2 = *(const float2*)(pre + off);
                float2 f2 = *(const float2*)(inf + off);
                v0 = 0.8f * fmaxf(v0, 0.f) + 0.1f * p2.x + 0.1f * f2.x;
                v1 = 0.8f * fmaxf(v1, 0.f) + 0.1f * p2.y + 0.1f * f2.y;
            }
            *(float2*)(C + off) = make_float2(v0, v1);
        }
    }
}

__global__ void __launch_bounds__(256, 2)
fc_in_kernel(const float* __restrict__ x, const float* __restrict__ w,
             const float* __restrict__ b)
{
    gemm_tc_body<IN_DIM, HID, 0>(x, w, b, nullptr, nullptr, g_in_feats);
}

__global__ void __launch_bounds__(256, 2)
layer_gemm_kernel(const float* __restrict__ w, int pre_sel, int out_sel)
{
    gemm_tc_body<N_TYPES * HID, HID, 1>(g_fout, w, nullptr,
                                        buf_ptr(pre_sel), g_in_feats,
                                        buf_ptr(out_sel));
}

__global__ void __launch_bounds__(256, 2)
fc_out_kernel(const float* __restrict__ w, const float* __restrict__ b,
              float* __restrict__ out, int feats_sel)
{
    gemm_tc_body<HID, OUT_DIM, 0>(buf_ptr(feats_sel), w, b, nullptr, nullptr, out);
}

// ============================================================================
// Gather (select-free): indices permuted by path type in smem, pre-scaled to
// float4 element offsets; weights pre-resolved+mean-scaled in g_wres.
// 1 warp per node, 8 nodes per 256-thread block.
// ============================================================================
__global__ void __launch_bounds__(256)
gather_kernel(const int* __restrict__ paths, const int* __restrict__ ptypes,
              int feats_sel)
{
    const float4* __restrict__ feats4 = (const float4*)buf_ptr(feats_sel);
    const float4* __restrict__ wres4  = (const float4*)g_wres;

    __shared__ int off_s[8][N_PATHS * PATH_LEN];
    __shared__ int types_s[N_PATHS];

    const int tid  = threadIdx.x;
    const int slot = tid >> 5;
    const int lane = tid & 31;
    const int n    = blockIdx.x * 8 + slot;

    if (tid < N_PATHS) types_s[tid] = ptypes[tid];
    __syncthreads();

    unsigned tmask = 0;
#pragma unroll
    for (int p = 0; p < N_PATHS; p++)
        tmask |= (types_s[p] ? 1u : 0u) << p;
    const int c0 = N_PATHS - __popc(tmask);

    {
        int i  = tid * 2;
        int sl = i >> 6;
        int r  = i & 63;
        int p  = r >> 3, l = r & 7;
        int nn = blockIdx.x * 8 + sl;
        int2 v = *(const int2*)(paths + (size_t)p * (N_NODES * PATH_LEN)
                                + (size_t)nn * PATH_LEN + l);
        unsigned below = (1u << p) - 1u;
        int pos = (tmask >> p) & 1
                ? c0 + __popc(tmask & below)
                : __popc(~tmask & below & 0xFFu);
        off_s[sl][pos * PATH_LEN + l]     = v.x * (HID / 4);
        off_s[sl][pos * PATH_LEN + l + 1] = v.y * (HID / 4);
    }
    __syncthreads();

    const float4* fb = feats4 + lane;
    const int* orow = off_s[slot];

    float4 acc0 = make_float4(0.f, 0.f, 0.f, 0.f);
    {
        float4 w[PATH_LEN];
#pragma unroll
        for (int l = 0; l < PATH_LEN; l++)
            w[l] = __ldg(wres4 + (size_t)l * (HID / 4) + lane);
        for (int pp = 0; pp < c0; pp++) {
            int4 o0 = *(const int4*)(orow + pp * PATH_LEN);
            int4 o1 = *(const int4*)(orow + pp * PATH_LEN + 4);
            float4 f0 = __ldg(fb + o0.x), f1 = __ldg(fb + o0.y);
            float4 f2 = __ldg(fb + o0.z), f3 = __ldg(fb + o0.w);
            float4 f4 = __ldg(fb + o1.x), f5 = __ldg(fb + o1.y);
            float4 f6 = __ldg(fb + o1.z), f7 = __ldg(fb + o1.w);
#define ACC(F, L) \
            acc0.x = fmaf(F.x, w[L].x, acc0.x); \
            acc0.y = fmaf(F.y, w[L].y, acc0.y); \
            acc0.z = fmaf(F.z, w[L].z, acc0.z); \
            acc0.w = fmaf(F.w, w[L].w, acc0.w);
            ACC(f0, 0) ACC(f1, 1) ACC(f2, 2) ACC(f3, 3)
            ACC(f4, 4) ACC(f5, 5) ACC(f6, 6) ACC(f7, 7)
#undef ACC
        }
    }
    float4 acc1 = make_float4(0.f, 0.f, 0.f, 0.f);
    {
        float4 w[PATH_LEN];
#pragma unroll
        for (int l = 0; l < PATH_LEN; l++)
            w[l] = __ldg(wres4 + (size_t)(PATH_LEN + l) * (HID / 4) + lane);
        for (int pp = c0; pp < N_PATHS; pp++) {
            int4 o0 = *(const int4*)(orow + pp * PATH_LEN);
            int4 o1 = *(const int4*)(orow + pp * PATH_LEN + 4);
            float4 f0 = __ldg(fb + o0.x), f1 = __ldg(fb + o0.y);
            float4 f2 = __ldg(fb + o0.z), f3 = __ldg(fb + o0.w);
            float4 f4 = __ldg(fb + o1.x), f5 = __ldg(fb + o1.y);
            float4 f6 = __ldg(fb + o1.z), f7 = __ldg(fb + o1.w);
#define ACC(F, L) \
            acc1.x = fmaf(F.x, w[L].x, acc1.x); \
            acc1.y = fmaf(F.y, w[L].y, acc1.y); \
            acc1.z = fmaf(F.z, w[L].z, acc1.z); \
            acc1.w = fmaf(F.w, w[L].w, acc1.w);
            ACC(f0, 0) ACC(f1, 1) ACC(f2, 2) ACC(f3, 3)
            ACC(f4, 4) ACC(f5, 5) ACC(f6, 6) ACC(f7, 7)
#undef ACC
        }
    }

    float4* fo4 = (float4*)(g_fout + (size_t)n * (N_TYPES * HID));
    fo4[lane]           = acc0;
    fo4[HID / 4 + lane] = acc1;
}

// ============================================================================
extern "C" void kernel_launch(void* const* d_in, const int* in_sizes, int n_in,
                              void* d_out, int out_size)
{
    const float* input_x    = (const float*)d_in[0];
    const int*   paths      = (const int*)d_in[1];
    const int*   ptypes     = (const int*)d_in[2];
    const float* fc_in_w    = (const float*)d_in[3];
    const float* fc_in_b    = (const float*)d_in[4];
    const float* fc_out_w   = (const float*)d_in[5];
    const float* fc_out_b   = (const float*)d_in[6];
    const float* layer_fc_w = (const float*)d_in[7];
    const float* path_w     = (const float*)d_in[8];
    float* out = (float*)d_out;

    const dim3 blk(256);
    const dim3 ggrd((N_NODES + 63) / 64);

    fc_in_kernel<<<ggrd, blk>>>(input_x, fc_in_w, fc_in_b);

    int cur = 0;  // feats = g_in_feats
    for (int i = 0; i < N_LAYERS; i++) {
        resolve_w_kernel<<<(N_TYPES * PATH_LEN * HID + 255) / 256, blk>>>(
            path_w + (size_t)i * N_TYPES * PATH_LEN * HID, ptypes);
        gather_kernel<<<N_NODES / 8, blk>>>(paths, ptypes, cur);
        int nxt = (cur == 1) ? 2 : 1;
        layer_gemm_kernel<<<ggrd, blk>>>(
            layer_fc_w + (size_t)i * HID * (N_TYPES * HID), cur, nxt);
        cur = nxt;
    }

    fc_out_kernel<<<ggrd, blk>>>(fc_out_w, fc_out_b, out, cur);
}

// round 7
// speedup vs baseline: 1.2758x; 1.1854x over previous
#include <cuda_runtime.h>
#include <cstdint>

#define N_NODES 20000
#define IN_DIM 256
#define HID 128
#define OUT_DIM 64
#define N_LAYERS 4
#define N_PATHS 8
#define PATH_LEN 8
#define N_TYPES 2

// -------- scratch (no allocations allowed; device globals) --------
__device__ float    g_in_feats[N_NODES * HID];
__device__ float    g_bufA[N_NODES * HID];
__device__ float    g_bufB[N_NODES * HID];
__device__ uint32_t g_fout[N_NODES * N_TYPES * HID];          // tf32 bits
__device__ float    g_wres[N_LAYERS * N_TYPES * PATH_LEN * HID];

__device__ __forceinline__ float* buf_ptr(int s) {
    return s == 0 ? g_in_feats : (s == 1 ? g_bufA : g_bufB);
}

__device__ __forceinline__ uint32_t f2tf32(float f) {
    uint32_t u;
    asm("cvt.rna.tf32.f32 %0, %1;" : "=r"(u) : "f"(f));
    return u;
}

__device__ __forceinline__ void mma_tf32(
    float& d0, float& d1, float& d2, float& d3,
    uint32_t a0, uint32_t a1, uint32_t a2, uint32_t a3,
    uint32_t b0, uint32_t b1)
{
    asm volatile(
        "mma.sync.aligned.m16n8k8.row.col.f32.tf32.tf32.f32 "
        "{%0,%1,%2,%3}, {%4,%5,%6,%7}, {%8,%9}, {%0,%1,%2,%3};\n"
        : "+f"(d0), "+f"(d1), "+f"(d2), "+f"(d3)
        : "r"(a0), "r"(a1), "r"(a2), "r"(a3), "r"(b0), "r"(b1));
}

__device__ __forceinline__ void cp_async16(uint32_t* smem_dst, const void* gsrc,
                                           int src_bytes) {
    uint32_t s = (uint32_t)__cvta_generic_to_shared(smem_dst);
    asm volatile("cp.async.cg.shared.global [%0], [%1], 16, %2;\n"
                 :: "r"(s), "l"(gsrc), "r"(src_bytes));
}
__device__ __forceinline__ void cp_async_commit() {
    asm volatile("cp.async.commit_group;\n");
}
template <int N>
__device__ __forceinline__ void cp_async_wait() {
    asm volatile("cp.async.wait_group %0;\n" :: "n"(N));
}

// ============================================================================
// Prep: wres[i][t][l][h] = pw[i][t][l][h] / count[t]   (all layers at once)
// ============================================================================
__global__ void resolve_all_w_kernel(const float* __restrict__ pw,
                                     const int* __restrict__ ptypes)
{
    int i = blockIdx.x * blockDim.x + threadIdx.x;
    if (i >= N_LAYERS * N_TYPES * PATH_LEN * HID) return;
    int t = (i / (PATH_LEN * HID)) % N_TYPES;
    int cnt = 0;
#pragma unroll
    for (int p = 0; p < N_PATHS; p++) cnt += (__ldg(ptypes + p) == t);
    float inv = cnt > 0 ? 1.0f / (float)cnt : 0.0f;
    g_wres[i] = __ldg(pw + i) * inv;
}

// ============================================================================
// TF32 tensor-core GEMM with 3-stage cp.async pipeline.
//   C[M, BN] = EPI( A[M, KDIM] @ W[BN, KDIM]^T )
//   EPI==0: relu(acc + bias[n]);  EPI==1: 0.8*relu(acc)+0.1*pre+0.1*inf
//   CVT_A: A in gmem is fp32 (convert at fragment load); else already tf32.
// Block tile 64 x BN, 256 threads (4 warps M x 2 warps N), warp 16 x (BN/2).
// ============================================================================
template <int KDIM, int BN, int EPI, bool CVT_A>
__global__ void __launch_bounds__(256, 2)
gemm_tc_kernel(const void* __restrict__ Araw, const float* __restrict__ W,
               const float* __restrict__ bias, const float* __restrict__ pre,
               const float* __restrict__ inf, float* __restrict__ C)
{
    constexpr int BM = 64, BK = 32, LDS_ = 36, NST = 3;
    constexpr int NT  = BN / 16;
    constexpr int ASZ = BM * LDS_, BSZ = BN * LDS_;
    constexpr int KTILES = KDIM / BK;
    constexpr int NCA = (BM * BK / 4) / 256;      // A 16B-chunks per thread (2)
    constexpr int NCB = (BN * BK / 4) / 256;      // B chunks per thread (4 or 2)

    extern __shared__ uint32_t smem[];
    uint32_t* As = smem;                // NST stages
    uint32_t* Bs = smem + NST * ASZ;

    const uint32_t* A = (const uint32_t*)Araw;   // fp32 or tf32 bits
    const int tid    = threadIdx.x;
    const int lane   = tid & 31;
    const int warp   = tid >> 5;
    const int warp_m = warp & 3;
    const int warp_n = warp >> 2;
    const int gid    = lane >> 2;
    const int tig    = lane & 3;
    const int m0     = blockIdx.x * BM;

    float acc[NT][4];
#pragma unroll
    for (int nt = 0; nt < NT; nt++)
#pragma unroll
        for (int r = 0; r < 4; r++) acc[nt][r] = 0.f;

    // copy-issue for k-tile kt into stage buffer b
    auto issue = [&](int kt, int b) {
#pragma unroll
        for (int i = 0; i < NCA; i++) {
            int c   = tid + i * 256;            // chunk id
            int row = c >> 3, col = (c & 7) << 2;
            int ok  = (m0 + row) < N_NODES ? 16 : 0;
            cp_async16(As + b * ASZ + row * LDS_ + col,
                       A + (size_t)(m0 + row) * KDIM + kt * BK + col, ok);
        }
#pragma unroll
        for (int i = 0; i < NCB; i++) {
            int c   = tid + i * 256;
            int row = c >> 3, col = (c & 7) << 2;
            cp_async16(Bs + b * BSZ + row * LDS_ + col,
                       W + (size_t)row * KDIM + kt * BK + col, 16);
        }
    };

    // prologue: stages 0..NST-2
#pragma unroll
    for (int s = 0; s < NST - 1; s++) {
        if (s < KTILES) issue(s, s);
        cp_async_commit();
    }

    for (int kt = 0; kt < KTILES; kt++) {
        if (kt + NST - 1 < KTILES) issue(kt + NST - 1, (kt + NST - 1) % NST);
        cp_async_commit();
        cp_async_wait<NST - 1>();
        __syncthreads();

        const uint32_t* Ab = As + (kt % NST) * ASZ;
        const uint32_t* Bb = Bs + (kt % NST) * BSZ;
#pragma unroll
        for (int kk = 0; kk < BK / 8; kk++) {
            const int kb = kk * 8;
            uint32_t a[4];
            {
                int r = warp_m * 16 + gid;
                a[0] = Ab[r * LDS_ + kb + tig];
                a[1] = Ab[(r + 8) * LDS_ + kb + tig];
                a[2] = Ab[r * LDS_ + kb + tig + 4];
                a[3] = Ab[(r + 8) * LDS_ + kb + tig + 4];
                if constexpr (CVT_A) {
#pragma unroll
                    for (int j = 0; j < 4; j++)
                        a[j] = f2tf32(__uint_as_float(a[j]));
                }
            }
            uint32_t b[NT][2];
#pragma unroll
            for (int nt = 0; nt < NT; nt++) {
                int c = warp_n * (NT * 8) + nt * 8 + gid;
                b[nt][0] = f2tf32(__uint_as_float(Bb[c * LDS_ + kb + tig]));
                b[nt][1] = f2tf32(__uint_as_float(Bb[c * LDS_ + kb + tig + 4]));
            }
#pragma unroll
            for (int nt = 0; nt < NT; nt++)
                mma_tf32(acc[nt][0], acc[nt][1], acc[nt][2], acc[nt][3],
                         a[0], a[1], a[2], a[3], b[nt][0], b[nt][1]);
        }
        __syncthreads();
    }

    // ---- epilogue ----
#pragma unroll
    for (int half = 0; half < 2; half++) {
        int row = m0 + warp_m * 16 + half * 8 + gid;
        if (row >= N_NODES) continue;
#pragma unroll
        for (int nt = 0; nt < NT; nt++) {
            int col = warp_n * (NT * 8) + nt * 8 + 2 * tig;
            float v0 = acc[nt][half * 2 + 0];
            float v1 = acc[nt][half * 2 + 1];
            size_t off = (size_t)row * BN + col;
            if constexpr (EPI == 0) {
                v0 = fmaxf(v0 + bias[col], 0.f);
                v1 = fmaxf(v1 + bias[col + 1], 0.f);
            } else {
                float2 p2 = *(const float2*)(pre + off);
                float2 f2 = *(const float2*)(inf + off);
                v0 = 0.8f * fmaxf(v0, 0.f) + 0.1f * p2.x + 0.1f * f2.x;
                v1 = 0.8f * fmaxf(v1, 0.f) + 0.1f * p2.y + 0.1f * f2.y;
            }
            *(float2*)(C + off) = make_float2(v0, v1);
        }
    }
}

// ============================================================================
// Gather (select-free), writes fout as tf32 bits:
// 1 warp per node, 8 nodes per 256-thread block.
// ============================================================================
__global__ void __launch_bounds__(256)
gather_kernel(const int* __restrict__ paths, const int* __restrict__ ptypes,
              int feats_sel, int layer)
{
    const float4* __restrict__ feats4 = (const float4*)buf_ptr(feats_sel);
    const float4* __restrict__ wres4  =
        (const float4*)(g_wres + (size_t)layer * N_TYPES * PATH_LEN * HID);

    __shared__ int off_s[8][N_PATHS * PATH_LEN];
    __shared__ int types_s[N_PATHS];

    const int tid  = threadIdx.x;
    const int slot = tid >> 5;
    const int lane = tid & 31;
    const int n    = blockIdx.x * 8 + slot;

    if (tid < N_PATHS) types_s[tid] = ptypes[tid];
    __syncthreads();

    unsigned tmask = 0;
#pragma unroll
    for (int p = 0; p < N_PATHS; p++)
        tmask |= (types_s[p] ? 1u : 0u) << p;
    const int c0 = N_PATHS - __popc(tmask);

    {
        int i  = tid * 2;
        int sl = i >> 6;
        int r  = i & 63;
        int p  = r >> 3, l = r & 7;
        int nn = blockIdx.x * 8 + sl;
        int2 v = *(const int2*)(paths + (size_t)p * (N_NODES * PATH_LEN)
                                + (size_t)nn * PATH_LEN + l);
        unsigned below = (1u << p) - 1u;
        int pos = (tmask >> p) & 1
                ? c0 + __popc(tmask & below)
                : __popc(~tmask & below & 0xFFu);
        off_s[sl][pos * PATH_LEN + l]     = v.x * (HID / 4);
        off_s[sl][pos * PATH_LEN + l + 1] = v.y * (HID / 4);
    }
    __syncthreads();

    const float4* fb = feats4 + lane;
    const int* orow = off_s[slot];

    float4 acc0 = make_float4(0.f, 0.f, 0.f, 0.f);
    {
        float4 w[PATH_LEN];
#pragma unroll
        for (int l = 0; l < PATH_LEN; l++)
            w[l] = __ldg(wres4 + (size_t)l * (HID / 4) + lane);
        for (int pp = 0; pp < c0; pp++) {
            int4 o0 = *(const int4*)(orow + pp * PATH_LEN);
            int4 o1 = *(const int4*)(orow + pp * PATH_LEN + 4);
            float4 f0 = __ldg(fb + o0.x), f1 = __ldg(fb + o0.y);
            float4 f2 = __ldg(fb + o0.z), f3 = __ldg(fb + o0.w);
            float4 f4 = __ldg(fb + o1.x), f5 = __ldg(fb + o1.y);
            float4 f6 = __ldg(fb + o1.z), f7 = __ldg(fb + o1.w);
#define ACC(F, L) \
            acc0.x = fmaf(F.x, w[L].x, acc0.x); \
            acc0.y = fmaf(F.y, w[L].y, acc0.y); \
            acc0.z = fmaf(F.z, w[L].z, acc0.z); \
            acc0.w = fmaf(F.w, w[L].w, acc0.w);
            ACC(f0, 0) ACC(f1, 1) ACC(f2, 2) ACC(f3, 3)
            ACC(f4, 4) ACC(f5, 5) ACC(f6, 6) ACC(f7, 7)
#undef ACC
        }
    }
    float4 acc1 = make_float4(0.f, 0.f, 0.f, 0.f);
    {
        float4 w[PATH_LEN];
#pragma unroll
        for (int l = 0; l < PATH_LEN; l++)
            w[l] = __ldg(wres4 + (size_t)(PATH_LEN + l) * (HID / 4) + lane);
        for (int pp = c0; pp < N_PATHS; pp++) {
            int4 o0 = *(const int4*)(orow + pp * PATH_LEN);
            int4 o1 = *(const int4*)(orow + pp * PATH_LEN + 4);
            float4 f0 = __ldg(fb + o0.x), f1 = __ldg(fb + o0.y);
            float4 f2 = __ldg(fb + o0.z), f3 = __ldg(fb + o0.w);
            float4 f4 = __ldg(fb + o1.x), f5 = __ldg(fb + o1.y);
            float4 f6 = __ldg(fb + o1.z), f7 = __ldg(fb + o1.w);
#define ACC(F, L) \
            acc1.x = fmaf(F.x, w[L].x, acc1.x); \
            acc1.y = fmaf(F.y, w[L].y, acc1.y); \
            acc1.z = fmaf(F.z, w[L].z, acc1.z); \
            acc1.w = fmaf(F.w, w[L].w, acc1.w);
            ACC(f0, 0) ACC(f1, 1) ACC(f2, 2) ACC(f3, 3)
            ACC(f4, 4) ACC(f5, 5) ACC(f6, 6) ACC(f7, 7)
#undef ACC
        }
    }

    // store tf32-converted (layer GEMM consumes A without cvt)
    uint4* fo4 = (uint4*)(g_fout + (size_t)n * (N_TYPES * HID));
    fo4[lane] = make_uint4(f2tf32(acc0.x), f2tf32(acc0.y),
                           f2tf32(acc0.z), f2tf32(acc0.w));
    fo4[HID / 4 + lane] = make_uint4(f2tf32(acc1.x), f2tf32(acc1.y),
                                     f2tf32(acc1.z), f2tf32(acc1.w));
}

// ============================================================================
extern "C" void kernel_launch(void* const* d_in, const int* in_sizes, int n_in,
                              void* d_out, int out_size)
{
    const float* input_x    = (const float*)d_in[0];
    const int*   paths      = (const int*)d_in[1];
    const int*   ptypes     = (const int*)d_in[2];
    const float* fc_in_w    = (const float*)d_in[3];
    const float* fc_in_b    = (const float*)d_in[4];
    const float* fc_out_w   = (const float*)d_in[5];
    const float* fc_out_b   = (const float*)d_in[6];
    const float* layer_fc_w = (const float*)d_in[7];
    const float* path_w     = (const float*)d_in[8];
    float* out = (float*)d_out;

    constexpr int LDS_ = 36, NST = 3;
    constexpr size_t SM_128 = (size_t)NST * (64 * LDS_ + 128 * LDS_) * 4; // 82944
    constexpr size_t SM_64  = (size_t)NST * (64 * LDS_ + 64 * LDS_) * 4;  // 55296

    static bool attr_done = false;
    if (!attr_done) {
        cudaFuncSetAttribute(gemm_tc_kernel<IN_DIM, HID, 0, true>,
                             cudaFuncAttributeMaxDynamicSharedMemorySize, SM_128);
        cudaFuncSetAttribute(gemm_tc_kernel<N_TYPES * HID, HID, 1, false>,
                             cudaFuncAttributeMaxDynamicSharedMemorySize, SM_128);
        cudaFuncSetAttribute(gemm_tc_kernel<HID, OUT_DIM, 0, true>,
                             cudaFuncAttributeMaxDynamicSharedMemorySize, SM_64);
        attr_done = true;
    }

    // resolve buffer pointers for device globals
    float *in_feats_p, *bufA_p, *bufB_p;
    uint32_t* fout_p;
    cudaGetSymbolAddress((void**)&in_feats_p, g_in_feats);
    cudaGetSymbolAddress((void**)&bufA_p, g_bufA);
    cudaGetSymbolAddress((void**)&bufB_p, g_bufB);
    cudaGetSymbolAddress((void**)&fout_p, g_fout);

    const dim3 blk(256);
    const dim3 ggrd((N_NODES + 63) / 64);

    resolve_all_w_kernel<<<(N_LAYERS * N_TYPES * PATH_LEN * HID + 255) / 256,
                           blk>>>(path_w, ptypes);

    gemm_tc_kernel<IN_DIM, HID, 0, true><<<ggrd, blk, SM_128>>>(
        input_x, fc_in_w, fc_in_b, nullptr, nullptr, in_feats_p);

    int cur = 0;  // feats = g_in_feats
    float* bufs[3] = {in_feats_p, bufA_p, bufB_p};
    for (int i = 0; i < N_LAYERS; i++) {
        gather_kernel<<<N_NODES / 8, blk>>>(paths, ptypes, cur, i);
        int nxt = (cur == 1) ? 2 : 1;
        gemm_tc_kernel<N_TYPES * HID, HID, 1, false><<<ggrd, blk, SM_128>>>(
            fout_p, layer_fc_w + (size_t)i * HID * (N_TYPES * HID), nullptr,
            bufs[cur], in_feats_p, bufs[nxt]);
        cur = nxt;
    }

    gemm_tc_kernel<HID, OUT_DIM, 0, true><<<ggrd, blk, SM_64>>>(
        bufs[cur], fc_out_w, fc_out_b, nullptr, nullptr, out);
}

// round 8
// speedup vs baseline: 1.3031x; 1.0214x over previous
#include <cuda_runtime.h>
#include <cstdint>

#define N_NODES 20000
#define IN_DIM 256
#define HID 128
#define OUT_DIM 64
#define N_LAYERS 4
#define N_PATHS 8
#define PATH_LEN 8
#define N_TYPES 2

// -------- scratch (no allocations allowed; device globals) --------
__device__ float    g_in_feats[N_NODES * HID];
__device__ float    g_bufA[N_NODES * HID];
__device__ float    g_bufB[N_NODES * HID];
__device__ uint32_t g_fout[N_NODES * N_TYPES * HID];          // tf32 bits
__device__ float    g_wres[N_LAYERS * N_TYPES * PATH_LEN * HID];

// pre-converted tf32 weights
#define W_IN_ELEMS    (HID * IN_DIM)
#define W_LAYER_ELEMS (N_LAYERS * HID * N_TYPES * HID)
#define W_OUT_ELEMS   (OUT_DIM * HID)
__device__ uint32_t g_w_in[W_IN_ELEMS];
__device__ uint32_t g_w_layer[W_LAYER_ELEMS];
__device__ uint32_t g_w_out[W_OUT_ELEMS];

__device__ __forceinline__ uint32_t f2tf32(float f) {
    uint32_t u;
    asm("cvt.rna.tf32.f32 %0, %1;" : "=r"(u) : "f"(f));
    return u;
}

__device__ __forceinline__ void mma_tf32(
    float& d0, float& d1, float& d2, float& d3,
    uint32_t a0, uint32_t a1, uint32_t a2, uint32_t a3,
    uint32_t b0, uint32_t b1)
{
    asm volatile(
        "mma.sync.aligned.m16n8k8.row.col.f32.tf32.tf32.f32 "
        "{%0,%1,%2,%3}, {%4,%5,%6,%7}, {%8,%9}, {%0,%1,%2,%3};\n"
        : "+f"(d0), "+f"(d1), "+f"(d2), "+f"(d3)
        : "r"(a0), "r"(a1), "r"(a2), "r"(a3), "r"(b0), "r"(b1));
}

__device__ __forceinline__ void cp_async16(uint32_t* smem_dst, const void* gsrc,
                                           int src_bytes) {
    uint32_t s = (uint32_t)__cvta_generic_to_shared(smem_dst);
    asm volatile("cp.async.cg.shared.global [%0], [%1], 16, %2;\n"
                 :: "r"(s), "l"(gsrc), "r"(src_bytes));
}
__device__ __forceinline__ void cp_async_commit() {
    asm volatile("cp.async.commit_group;\n");
}
template <int N>
__device__ __forceinline__ void cp_async_wait() {
    asm volatile("cp.async.wait_group %0;\n" :: "n"(N));
}

// ============================================================================
// Prep 1: wres[i][t][l][h] = pw[i][t][l][h] / count[t]
// Prep 2: convert all GEMM weights to tf32 bits
// ============================================================================
__global__ void resolve_all_w_kernel(const float* __restrict__ pw,
                                     const int* __restrict__ ptypes)
{
    int i = blockIdx.x * blockDim.x + threadIdx.x;
    if (i >= N_LAYERS * N_TYPES * PATH_LEN * HID) return;
    int t = (i / (PATH_LEN * HID)) % N_TYPES;
    int cnt = 0;
#pragma unroll
    for (int p = 0; p < N_PATHS; p++) cnt += (__ldg(ptypes + p) == t);
    float inv = cnt > 0 ? 1.0f / (float)cnt : 0.0f;
    g_wres[i] = __ldg(pw + i) * inv;
}

__global__ void convert_w_kernel(const float* __restrict__ w_in,
                                 const float* __restrict__ w_layer,
                                 const float* __restrict__ w_out)
{
    int i = blockIdx.x * blockDim.x + threadIdx.x;
    if (i < W_IN_ELEMS)    g_w_in[i]    = f2tf32(__ldg(w_in + i));
    if (i < W_LAYER_ELEMS) g_w_layer[i] = f2tf32(__ldg(w_layer + i));
    if (i < W_OUT_ELEMS)   g_w_out[i]   = f2tf32(__ldg(w_out + i));
}

// ============================================================================
// TF32 tensor-core GEMM, 3-stage cp.async pipeline, tf32 weights.
//   C[M, BN] = EPI( A[M, KDIM] @ W[BN, KDIM]^T )
//   EPI==0: relu(acc + bias[n]);  EPI==1: 0.8*relu(acc)+0.1*pre+0.1*inf
//   CVT_A: A in gmem is fp32 (convert at fragment load); else tf32 bits.
// Block tile 64 x BN, 256 threads: 2 warps M x 4 warps N, warp tile 32 x (BN/4).
// ============================================================================
template <int KDIM, int BN, int EPI, bool CVT_A>
__global__ void __launch_bounds__(256, 2)
gemm_tc_kernel(const void* __restrict__ Araw, const uint32_t* __restrict__ W,
               const float* __restrict__ bias, const float* __restrict__ pre,
               const float* __restrict__ inf, float* __restrict__ C)
{
    constexpr int BM = 64, BK = 32, LDS_ = 36, NST = 3;
    constexpr int NTW = BN / 32;                  // n8-tiles per warp (4 or 2)
    constexpr int ASZ = BM * LDS_, BSZ = BN * LDS_;
    constexpr int KTILES = KDIM / BK;
    constexpr int NCA = (BM * BK / 4) / 256;
    constexpr int NCB = (BN * BK / 4) / 256;

    extern __shared__ uint32_t smem[];
    uint32_t* As = smem;
    uint32_t* Bs = smem + NST * ASZ;

    const uint32_t* A = (const uint32_t*)Araw;
    const int tid    = threadIdx.x;
    const int lane   = tid & 31;
    const int warp   = tid >> 5;
    const int warp_m = warp & 1;          // 32 rows each
    const int warp_n = warp >> 1;         // NTW*8 cols each
    const int gid    = lane >> 2;
    const int tig    = lane & 3;
    const int m0     = blockIdx.x * BM;

    float acc[2][NTW][4];
#pragma unroll
    for (int mt = 0; mt < 2; mt++)
#pragma unroll
        for (int nt = 0; nt < NTW; nt++)
#pragma unroll
            for (int r = 0; r < 4; r++) acc[mt][nt][r] = 0.f;

    auto issue = [&](int kt, int b) {
#pragma unroll
        for (int i = 0; i < NCA; i++) {
            int c   = tid + i * 256;
            int row = c >> 3, col = (c & 7) << 2;
            int ok  = (m0 + row) < N_NODES ? 16 : 0;
            cp_async16(As + b * ASZ + row * LDS_ + col,
                       A + (size_t)(m0 + row) * KDIM + kt * BK + col, ok);
        }
#pragma unroll
        for (int i = 0; i < NCB; i++) {
            int c   = tid + i * 256;
            int row = c >> 3, col = (c & 7) << 2;
            cp_async16(Bs + b * BSZ + row * LDS_ + col,
                       W + (size_t)row * KDIM + kt * BK + col, 16);
        }
    };

#pragma unroll
    for (int s = 0; s < NST - 1; s++) {
        if (s < KTILES) issue(s, s);
        cp_async_commit();
    }

    for (int kt = 0; kt < KTILES; kt++) {
        if (kt + NST - 1 < KTILES) issue(kt + NST - 1, (kt + NST - 1) % NST);
        cp_async_commit();
        cp_async_wait<NST - 1>();
        __syncthreads();

        const uint32_t* Ab = As + (kt % NST) * ASZ;
        const uint32_t* Bb = Bs + (kt % NST) * BSZ;
#pragma unroll
        for (int kk = 0; kk < BK / 8; kk++) {
            const int kb = kk * 8;
            uint32_t a[2][4];
#pragma unroll
            for (int mt = 0; mt < 2; mt++) {
                int r = warp_m * 32 + mt * 16 + gid;
                a[mt][0] = Ab[r * LDS_ + kb + tig];
                a[mt][1] = Ab[(r + 8) * LDS_ + kb + tig];
                a[mt][2] = Ab[r * LDS_ + kb + tig + 4];
                a[mt][3] = Ab[(r + 8) * LDS_ + kb + tig + 4];
                if constexpr (CVT_A) {
#pragma unroll
                    for (int j = 0; j < 4; j++)
                        a[mt][j] = f2tf32(__uint_as_float(a[mt][j]));
                }
            }
            uint32_t b[NTW][2];
#pragma unroll
            for (int nt = 0; nt < NTW; nt++) {
                int c = warp_n * (NTW * 8) + nt * 8 + gid;
                b[nt][0] = Bb[c * LDS_ + kb + tig];
                b[nt][1] = Bb[c * LDS_ + kb + tig + 4];
            }
#pragma unroll
            for (int mt = 0; mt < 2; mt++)
#pragma unroll
                for (int nt = 0; nt < NTW; nt++)
                    mma_tf32(acc[mt][nt][0], acc[mt][nt][1],
                             acc[mt][nt][2], acc[mt][nt][3],
                             a[mt][0], a[mt][1], a[mt][2], a[mt][3],
                             b[nt][0], b[nt][1]);
        }
        __syncthreads();
    }

    // ---- epilogue ----
#pragma unroll
    for (int mt = 0; mt < 2; mt++) {
#pragma unroll
        for (int half = 0; half < 2; half++) {
            int row = m0 + warp_m * 32 + mt * 16 + half * 8 + gid;
            if (row >= N_NODES) continue;
#pragma unroll
            for (int nt = 0; nt < NTW; nt++) {
                int col = warp_n * (NTW * 8) + nt * 8 + 2 * tig;
                float v0 = acc[mt][nt][half * 2 + 0];
                float v1 = acc[mt][nt][half * 2 + 1];
                size_t off = (size_t)row * BN + col;
                if constexpr (EPI == 0) {
                    v0 = fmaxf(v0 + bias[col], 0.f);
                    v1 = fmaxf(v1 + bias[col + 1], 0.f);
                } else {
                    float2 p2 = *(const float2*)(pre + off);
                    float2 f2 = *(const float2*)(inf + off);
                    v0 = 0.8f * fmaxf(v0, 0.f) + 0.1f * p2.x + 0.1f * f2.x;
                    v1 = 0.8f * fmaxf(v1, 0.f) + 0.1f * p2.y + 0.1f * f2.y;
                }
                *(float2*)(C + off) = make_float2(v0, v1);
            }
        }
    }
}

// ============================================================================
// Gather (select-free), writes fout as tf32 bits:
// 1 warp per node, 8 nodes per 256-thread block.
// ============================================================================
__device__ __forceinline__ float* buf_ptr(int s) {
    return s == 0 ? g_in_feats : (s == 1 ? g_bufA : g_bufB);
}

__global__ void __launch_bounds__(256)
gather_kernel(const int* __restrict__ paths, const int* __restrict__ ptypes,
              int feats_sel, int layer)
{
    const float4* __restrict__ feats4 = (const float4*)buf_ptr(feats_sel);
    const float4* __restrict__ wres4  =
        (const float4*)(g_wres + (size_t)layer * N_TYPES * PATH_LEN * HID);

    __shared__ int off_s[8][N_PATHS * PATH_LEN];
    __shared__ int types_s[N_PATHS];

    const int tid  = threadIdx.x;
    const int slot = tid >> 5;
    const int lane = tid & 31;
    const int n    = blockIdx.x * 8 + slot;

    if (tid < N_PATHS) types_s[tid] = ptypes[tid];
    __syncthreads();

    unsigned tmask = 0;
#pragma unroll
    for (int p = 0; p < N_PATHS; p++)
        tmask |= (types_s[p] ? 1u : 0u) << p;
    const int c0 = N_PATHS - __popc(tmask);

    {
        int i  = tid * 2;
        int sl = i >> 6;
        int r  = i & 63;
        int p  = r >> 3, l = r & 7;
        int nn = blockIdx.x * 8 + sl;
        int2 v = *(const int2*)(paths + (size_t)p * (N_NODES * PATH_LEN)
                                + (size_t)nn * PATH_LEN + l);
        unsigned below = (1u << p) - 1u;
        int pos = (tmask >> p) & 1
                ? c0 + __popc(tmask & below)
                : __popc(~tmask & below & 0xFFu);
        off_s[sl][pos * PATH_LEN + l]     = v.x * (HID / 4);
        off_s[sl][pos * PATH_LEN + l + 1] = v.y * (HID / 4);
    }
    __syncthreads();

    const float4* fb = feats4 + lane;
    const int* orow = off_s[slot];

    float4 acc0 = make_float4(0.f, 0.f, 0.f, 0.f);
    {
        float4 w[PATH_LEN];
#pragma unroll
        for (int l = 0; l < PATH_LEN; l++)
            w[l] = __ldg(wres4 + (size_t)l * (HID / 4) + lane);
        for (int pp = 0; pp < c0; pp++) {
            int4 o0 = *(const int4*)(orow + pp * PATH_LEN);
            int4 o1 = *(const int4*)(orow + pp * PATH_LEN + 4);
            float4 f0 = __ldg(fb + o0.x), f1 = __ldg(fb + o0.y);
            float4 f2 = __ldg(fb + o0.z), f3 = __ldg(fb + o0.w);
            float4 f4 = __ldg(fb + o1.x), f5 = __ldg(fb + o1.y);
            float4 f6 = __ldg(fb + o1.z), f7 = __ldg(fb + o1.w);
#define ACC(F, L) \
            acc0.x = fmaf(F.x, w[L].x, acc0.x); \
            acc0.y = fmaf(F.y, w[L].y, acc0.y); \
            acc0.z = fmaf(F.z, w[L].z, acc0.z); \
            acc0.w = fmaf(F.w, w[L].w, acc0.w);
            ACC(f0, 0) ACC(f1, 1) ACC(f2, 2) ACC(f3, 3)
            ACC(f4, 4) ACC(f5, 5) ACC(f6, 6) ACC(f7, 7)
#undef ACC
        }
    }
    float4 acc1 = make_float4(0.f, 0.f, 0.f, 0.f);
    {
        float4 w[PATH_LEN];
#pragma unroll
        for (int l = 0; l < PATH_LEN; l++)
            w[l] = __ldg(wres4 + (size_t)(PATH_LEN + l) * (HID / 4) + lane);
        for (int pp = c0; pp < N_PATHS; pp++) {
            int4 o0 = *(const int4*)(orow + pp * PATH_LEN);
            int4 o1 = *(const int4*)(orow + pp * PATH_LEN + 4);
            float4 f0 = __ldg(fb + o0.x), f1 = __ldg(fb + o0.y);
            float4 f2 = __ldg(fb + o0.z), f3 = __ldg(fb + o0.w);
            float4 f4 = __ldg(fb + o1.x), f5 = __ldg(fb + o1.y);
            float4 f6 = __ldg(fb + o1.z), f7 = __ldg(fb + o1.w);
#define ACC(F, L) \
            acc1.x = fmaf(F.x, w[L].x, acc1.x); \
            acc1.y = fmaf(F.y, w[L].y, acc1.y); \
            acc1.z = fmaf(F.z, w[L].z, acc1.z); \
            acc1.w = fmaf(F.w, w[L].w, acc1.w);
            ACC(f0, 0) ACC(f1, 1) ACC(f2, 2) ACC(f3, 3)
            ACC(f4, 4) ACC(f5, 5) ACC(f6, 6) ACC(f7, 7)
#undef ACC
        }
    }

    uint4* fo4 = (uint4*)(g_fout + (size_t)n * (N_TYPES * HID));
    fo4[lane] = make_uint4(f2tf32(acc0.x), f2tf32(acc0.y),
                           f2tf32(acc0.z), f2tf32(acc0.w));
    fo4[HID / 4 + lane] = make_uint4(f2tf32(acc1.x), f2tf32(acc1.y),
                                     f2tf32(acc1.z), f2tf32(acc1.w));
}

// ============================================================================
extern "C" void kernel_launch(void* const* d_in, const int* in_sizes, int n_in,
                              void* d_out, int out_size)
{
    const float* input_x    = (const float*)d_in[0];
    const int*   paths      = (const int*)d_in[1];
    const int*   ptypes     = (const int*)d_in[2];
    const float* fc_in_w    = (const float*)d_in[3];
    const float* fc_in_b    = (const float*)d_in[4];
    const float* fc_out_w   = (const float*)d_in[5];
    const float* fc_out_b   = (const float*)d_in[6];
    const float* layer_fc_w = (const float*)d_in[7];
    const float* path_w     = (const float*)d_in[8];
    float* out = (float*)d_out;

    constexpr int LDS_ = 36, NST = 3;
    constexpr size_t SM_128 = (size_t)NST * (64 * LDS_ + 128 * LDS_) * 4; // 82944
    constexpr size_t SM_64  = (size_t)NST * (64 * LDS_ + 64 * LDS_) * 4;  // 55296

    static bool attr_done = false;
    if (!attr_done) {
        cudaFuncSetAttribute(gemm_tc_kernel<IN_DIM, HID, 0, true>,
                             cudaFuncAttributeMaxDynamicSharedMemorySize, SM_128);
        cudaFuncSetAttribute(gemm_tc_kernel<N_TYPES * HID, HID, 1, false>,
                             cudaFuncAttributeMaxDynamicSharedMemorySize, SM_128);
        cudaFuncSetAttribute(gemm_tc_kernel<HID, OUT_DIM, 0, true>,
                             cudaFuncAttributeMaxDynamicSharedMemorySize, SM_64);
        attr_done = true;
    }

    float *in_feats_p, *bufA_p, *bufB_p;
    uint32_t *fout_p, *w_in_p, *w_layer_p, *w_out_p;
    cudaGetSymbolAddress((void**)&in_feats_p, g_in_feats);
    cudaGetSymbolAddress((void**)&bufA_p, g_bufA);
    cudaGetSymbolAddress((void**)&bufB_p, g_bufB);
    cudaGetSymbolAddress((void**)&fout_p, g_fout);
    cudaGetSymbolAddress((void**)&w_in_p, g_w_in);
    cudaGetSymbolAddress((void**)&w_layer_p, g_w_layer);
    cudaGetSymbolAddress((void**)&w_out_p, g_w_out);

    const dim3 blk(256);
    const dim3 ggrd((N_NODES + 63) / 64);

    resolve_all_w_kernel<<<(N_LAYERS * N_TYPES * PATH_LEN * HID + 255) / 256,
                           blk>>>(path_w, ptypes);
    convert_w_kernel<<<(W_LAYER_ELEMS + 255) / 256, blk>>>(
        fc_in_w, layer_fc_w, fc_out_w);

    gemm_tc_kernel<IN_DIM, HID, 0, true><<<ggrd, blk, SM_128>>>(
        input_x, w_in_p, fc_in_b, nullptr, nullptr, in_feats_p);

    int cur = 0;  // feats = g_in_feats
    float* bufs[3] = {in_feats_p, bufA_p, bufB_p};
    for (int i = 0; i < N_LAYERS; i++) {
        gather_kernel<<<N_NODES / 8, blk>>>(paths, ptypes, cur, i);
        int nxt = (cur == 1) ? 2 : 1;
        gemm_tc_kernel<N_TYPES * HID, HID, 1, false><<<ggrd, blk, SM_128>>>(
            fout_p, w_layer_p + (size_t)i * HID * (N_TYPES * HID), nullptr,
            bufs[cur], in_feats_p, bufs[nxt]);
        cur = nxt;
    }

    gemm_tc_kernel<HID, OUT_DIM, 0, true><<<ggrd, blk, SM_64>>>(
        bufs[cur], w_out_p, fc_out_b, nullptr, nullptr, out);
}

// round 9
// speedup vs baseline: 1.3611x; 1.0445x over previous
#include <cuda_runtime.h>
#include <cstdint>

#define N_NODES 20000
#define IN_DIM 256
#define HID 128
#define OUT_DIM 64
#define N_LAYERS 4
#define N_PATHS 8
#define PATH_LEN 8
#define N_TYPES 2

// -------- scratch (no allocations allowed; device globals) --------
__device__ float    g_in_feats[N_NODES * HID];
__device__ float    g_bufA[N_NODES * HID];
__device__ float    g_bufB[N_NODES * HID];
__device__ uint32_t g_fout[N_NODES * N_TYPES * HID];          // tf32 bits
__device__ float    g_wres[N_LAYERS * N_TYPES * PATH_LEN * HID];

// pre-converted tf32 weights
#define W_IN_ELEMS    (HID * IN_DIM)
#define W_LAYER_ELEMS (N_LAYERS * HID * N_TYPES * HID)
#define W_OUT_ELEMS   (OUT_DIM * HID)
__device__ uint32_t g_w_in[W_IN_ELEMS];
__device__ uint32_t g_w_layer[W_LAYER_ELEMS];
__device__ uint32_t g_w_out[W_OUT_ELEMS];

__device__ __forceinline__ uint32_t f2tf32(float f) {
    uint32_t u;
    asm("cvt.rna.tf32.f32 %0, %1;" : "=r"(u) : "f"(f));
    return u;
}

__device__ __forceinline__ void mma_tf32(
    float& d0, float& d1, float& d2, float& d3,
    uint32_t a0, uint32_t a1, uint32_t a2, uint32_t a3,
    uint32_t b0, uint32_t b1)
{
    asm volatile(
        "mma.sync.aligned.m16n8k8.row.col.f32.tf32.tf32.f32 "
        "{%0,%1,%2,%3}, {%4,%5,%6,%7}, {%8,%9}, {%0,%1,%2,%3};\n"
        : "+f"(d0), "+f"(d1), "+f"(d2), "+f"(d3)
        : "r"(a0), "r"(a1), "r"(a2), "r"(a3), "r"(b0), "r"(b1));
}

__device__ __forceinline__ void cp_async16(uint32_t* smem_dst, const void* gsrc,
                                           int src_bytes) {
    uint32_t s = (uint32_t)__cvta_generic_to_shared(smem_dst);
    asm volatile("cp.async.cg.shared.global [%0], [%1], 16, %2;\n"
                 :: "r"(s), "l"(gsrc), "r"(src_bytes));
}
__device__ __forceinline__ void cp_async_commit() {
    asm volatile("cp.async.commit_group;\n");
}
template <int N>
__device__ __forceinline__ void cp_async_wait() {
    asm volatile("cp.async.wait_group %0;\n" :: "n"(N));
}

// ============================================================================
// Prep 1: wres[i][t][l][h] = pw[i][t][l][h] / count[t]
// Prep 2: convert all GEMM weights to tf32 bits
// ============================================================================
__global__ void resolve_all_w_kernel(const float* __restrict__ pw,
                                     const int* __restrict__ ptypes)
{
    int i = blockIdx.x * blockDim.x + threadIdx.x;
    if (i >= N_LAYERS * N_TYPES * PATH_LEN * HID) return;
    int t = (i / (PATH_LEN * HID)) % N_TYPES;
    int cnt = 0;
#pragma unroll
    for (int p = 0; p < N_PATHS; p++) cnt += (__ldg(ptypes + p) == t);
    float inv = cnt > 0 ? 1.0f / (float)cnt : 0.0f;
    g_wres[i] = __ldg(pw + i) * inv;
}

__global__ void convert_w_kernel(const float* __restrict__ w_in,
                                 const float* __restrict__ w_layer,
                                 const float* __restrict__ w_out)
{
    int i = blockIdx.x * blockDim.x + threadIdx.x;
    if (i < W_IN_ELEMS)    g_w_in[i]    = f2tf32(__ldg(w_in + i));
    if (i < W_LAYER_ELEMS) g_w_layer[i] = f2tf32(__ldg(w_layer + i));
    if (i < W_OUT_ELEMS)   g_w_out[i]   = f2tf32(__ldg(w_out + i));
}

// ============================================================================
// TF32 tensor-core GEMM, 3-stage cp.async pipeline, tf32 weights.
//   C[M, BN] = EPI( A[M, KDIM] @ W[BN, KDIM]^T )
//   EPI==0: relu(acc + bias[n]);  EPI==1: 0.8*relu(acc)+0.1*pre+0.1*inf
//   CVT_A: A in gmem is fp32 (convert at fragment load); else tf32 bits.
// Block tile 64 x BN, 256 threads: 2 warps M x 4 warps N, warp tile 32 x (BN/4).
// ============================================================================
template <int KDIM, int BN, int EPI, bool CVT_A>
__global__ void __launch_bounds__(256, 2)
gemm_tc_kernel(const void* __restrict__ Araw, const uint32_t* __restrict__ W,
               const float* __restrict__ bias, const float* __restrict__ pre,
               const float* __restrict__ inf, float* __restrict__ C)
{
    constexpr int BM = 64, BK = 32, LDS_ = 36, NST = 3;
    constexpr int NTW = BN / 32;
    constexpr int ASZ = BM * LDS_, BSZ = BN * LDS_;
    constexpr int KTILES = KDIM / BK;
    constexpr int NCA = (BM * BK / 4) / 256;
    constexpr int NCB = (BN * BK / 4) / 256;

    extern __shared__ uint32_t smem[];
    uint32_t* As = smem;
    uint32_t* Bs = smem + NST * ASZ;

    const uint32_t* A = (const uint32_t*)Araw;
    const int tid    = threadIdx.x;
    const int lane   = tid & 31;
    const int warp   = tid >> 5;
    const int warp_m = warp & 1;
    const int warp_n = warp >> 1;
    const int gid    = lane >> 2;
    const int tig    = lane & 3;
    const int m0     = blockIdx.x * BM;

    float acc[2][NTW][4];
#pragma unroll
    for (int mt = 0; mt < 2; mt++)
#pragma unroll
        for (int nt = 0; nt < NTW; nt++)
#pragma unroll
            for (int r = 0; r < 4; r++) acc[mt][nt][r] = 0.f;

    auto issue = [&](int kt, int b) {
#pragma unroll
        for (int i = 0; i < NCA; i++) {
            int c   = tid + i * 256;
            int row = c >> 3, col = (c & 7) << 2;
            int ok  = (m0 + row) < N_NODES ? 16 : 0;
            cp_async16(As + b * ASZ + row * LDS_ + col,
                       A + (size_t)(m0 + row) * KDIM + kt * BK + col, ok);
        }
#pragma unroll
        for (int i = 0; i < NCB; i++) {
            int c   = tid + i * 256;
            int row = c >> 3, col = (c & 7) << 2;
            cp_async16(Bs + b * BSZ + row * LDS_ + col,
                       W + (size_t)row * KDIM + kt * BK + col, 16);
        }
    };

#pragma unroll
    for (int s = 0; s < NST - 1; s++) {
        if (s < KTILES) issue(s, s);
        cp_async_commit();
    }

    for (int kt = 0; kt < KTILES; kt++) {
        if (kt + NST - 1 < KTILES) issue(kt + NST - 1, (kt + NST - 1) % NST);
        cp_async_commit();
        cp_async_wait<NST - 1>();
        __syncthreads();

        const uint32_t* Ab = As + (kt % NST) * ASZ;
        const uint32_t* Bb = Bs + (kt % NST) * BSZ;
#pragma unroll
        for (int kk = 0; kk < BK / 8; kk++) {
            const int kb = kk * 8;
            uint32_t a[2][4];
#pragma unroll
            for (int mt = 0; mt < 2; mt++) {
                int r = warp_m * 32 + mt * 16 + gid;
                a[mt][0] = Ab[r * LDS_ + kb + tig];
                a[mt][1] = Ab[(r + 8) * LDS_ + kb + tig];
                a[mt][2] = Ab[r * LDS_ + kb + tig + 4];
                a[mt][3] = Ab[(r + 8) * LDS_ + kb + tig + 4];
                if constexpr (CVT_A) {
#pragma unroll
                    for (int j = 0; j < 4; j++)
                        a[mt][j] = f2tf32(__uint_as_float(a[mt][j]));
                }
            }
            uint32_t b[NTW][2];
#pragma unroll
            for (int nt = 0; nt < NTW; nt++) {
                int c = warp_n * (NTW * 8) + nt * 8 + gid;
                b[nt][0] = Bb[c * LDS_ + kb + tig];
                b[nt][1] = Bb[c * LDS_ + kb + tig + 4];
            }
#pragma unroll
            for (int mt = 0; mt < 2; mt++)
#pragma unroll
                for (int nt = 0; nt < NTW; nt++)
                    mma_tf32(acc[mt][nt][0], acc[mt][nt][1],
                             acc[mt][nt][2], acc[mt][nt][3],
                             a[mt][0], a[mt][1], a[mt][2], a[mt][3],
                             b[nt][0], b[nt][1]);
        }
        __syncthreads();
    }

#pragma unroll
    for (int mt = 0; mt < 2; mt++) {
#pragma unroll
        for (int half = 0; half < 2; half++) {
            int row = m0 + warp_m * 32 + mt * 16 + half * 8 + gid;
            if (row >= N_NODES) continue;
#pragma unroll
            for (int nt = 0; nt < NTW; nt++) {
                int col = warp_n * (NTW * 8) + nt * 8 + 2 * tig;
                float v0 = acc[mt][nt][half * 2 + 0];
                float v1 = acc[mt][nt][half * 2 + 1];
                size_t off = (size_t)row * BN + col;
                if constexpr (EPI == 0) {
                    v0 = fmaxf(v0 + bias[col], 0.f);
                    v1 = fmaxf(v1 + bias[col + 1], 0.f);
                } else {
                    float2 p2 = *(const float2*)(pre + off);
                    float2 f2 = *(const float2*)(inf + off);
                    v0 = 0.8f * fmaxf(v0, 0.f) + 0.1f * p2.x + 0.1f * f2.x;
                    v1 = 0.8f * fmaxf(v1, 0.f) + 0.1f * p2.y + 0.1f * f2.y;
                }
                *(float2*)(C + off) = make_float2(v0, v1);
            }
        }
    }
}

// ============================================================================
// Gather, l-outer factored form:
//   acc_t = sum_l wres[t][l] * (sum_{p of type t} feats[idx[p,l]])
// Indices stored l-major, type-permuted (type-0 paths first). The type split
// is a compile-time constant C0 (dispatched by uniform switch), so the inner
// reduction has no selects and only 2 float4 weights live per l.
// 1 warp per node, 8 nodes per 256-thread block.
// ============================================================================
__device__ __forceinline__ float* buf_ptr(int s) {
    return s == 0 ? g_in_feats : (s == 1 ? g_bufA : g_bufB);
}

template <int C0>
__device__ __forceinline__ void gather_core(
    const float4* __restrict__ fb, const int* __restrict__ orow,
    const float4* __restrict__ wres4, int lane,
    float4& acc0, float4& acc1)
{
#pragma unroll
    for (int l = 0; l < PATH_LEN; l++) {
        int4 o0 = *(const int4*)(orow + l * N_PATHS);
        int4 o1 = *(const int4*)(orow + l * N_PATHS + 4);
        float4 f0 = __ldg(fb + o0.x), f1 = __ldg(fb + o0.y);
        float4 f2 = __ldg(fb + o0.z), f3 = __ldg(fb + o0.w);
        float4 f4 = __ldg(fb + o1.x), f5 = __ldg(fb + o1.y);
        float4 f6 = __ldg(fb + o1.z), f7 = __ldg(fb + o1.w);
        float4 w0 = __ldg(wres4 + (size_t)l * (HID / 4) + lane);
        float4 w1 = __ldg(wres4 + (size_t)(PATH_LEN + l) * (HID / 4) + lane);

        float4 s0 = make_float4(0.f, 0.f, 0.f, 0.f);
        float4 s1 = make_float4(0.f, 0.f, 0.f, 0.f);
#define PUT(I, F) \
        if constexpr (I < C0) { s0.x += F.x; s0.y += F.y; s0.z += F.z; s0.w += F.w; } \
        else                  { s1.x += F.x; s1.y += F.y; s1.z += F.z; s1.w += F.w; }
        PUT(0, f0) PUT(1, f1) PUT(2, f2) PUT(3, f3)
        PUT(4, f4) PUT(5, f5) PUT(6, f6) PUT(7, f7)
#undef PUT
        acc0.x = fmaf(s0.x, w0.x, acc0.x);
        acc0.y = fmaf(s0.y, w0.y, acc0.y);
        acc0.z = fmaf(s0.z, w0.z, acc0.z);
        acc0.w = fmaf(s0.w, w0.w, acc0.w);
        acc1.x = fmaf(s1.x, w1.x, acc1.x);
        acc1.y = fmaf(s1.y, w1.y, acc1.y);
        acc1.z = fmaf(s1.z, w1.z, acc1.z);
        acc1.w = fmaf(s1.w, w1.w, acc1.w);
    }
}

__global__ void __launch_bounds__(256, 4)
gather_kernel(const int* __restrict__ paths, const int* __restrict__ ptypes,
              int feats_sel, int layer)
{
    const float4* __restrict__ feats4 = (const float4*)buf_ptr(feats_sel);
    const float4* __restrict__ wres4  =
        (const float4*)(g_wres + (size_t)layer * N_TYPES * PATH_LEN * HID);

    __shared__ int off_s[8][N_PATHS * PATH_LEN];   // [slot][l*8 + pos]
    __shared__ int types_s[N_PATHS];

    const int tid  = threadIdx.x;
    const int slot = tid >> 5;
    const int lane = tid & 31;
    const int n    = blockIdx.x * 8 + slot;

    if (tid < N_PATHS) types_s[tid] = ptypes[tid];
    __syncthreads();

    unsigned tmask = 0;
#pragma unroll
    for (int p = 0; p < N_PATHS; p++)
        tmask |= (types_s[p] ? 1u : 0u) << p;
    const int c0 = N_PATHS - __popc(tmask);

    // fill l-major, type-permuted, pre-scaled offsets (2 per thread)
    {
        int i  = tid * 2;
        int sl = i >> 6;
        int r  = i & 63;
        int p  = r >> 3, l = r & 7;
        int nn = blockIdx.x * 8 + sl;
        int2 v = *(const int2*)(paths + (size_t)p * (N_NODES * PATH_LEN)
                                + (size_t)nn * PATH_LEN + l);
        unsigned below = (1u << p) - 1u;
        int pos = (tmask >> p) & 1
                ? c0 + __popc(tmask & below)
                : __popc(~tmask & below & 0xFFu);
        off_s[sl][l * N_PATHS + pos]       = v.x * (HID / 4);
        off_s[sl][(l + 1) * N_PATHS + pos] = v.y * (HID / 4);
    }
    __syncthreads();

    const float4* fb = feats4 + lane;
    const int* orow = off_s[slot];

    float4 acc0 = make_float4(0.f, 0.f, 0.f, 0.f);
    float4 acc1 = make_float4(0.f, 0.f, 0.f, 0.f);

    switch (c0) {
        case 0: gather_core<0>(fb, orow, wres4, lane, acc0, acc1); break;
        case 1: gather_core<1>(fb, orow, wres4, lane, acc0, acc1); break;
        case 2: gather_core<2>(fb, orow, wres4, lane, acc0, acc1); break;
        case 3: gather_core<3>(fb, orow, wres4, lane, acc0, acc1); break;
        case 4: gather_core<4>(fb, orow, wres4, lane, acc0, acc1); break;
        case 5: gather_core<5>(fb, orow, wres4, lane, acc0, acc1); break;
        case 6: gather_core<6>(fb, orow, wres4, lane, acc0, acc1); break;
        case 7: gather_core<7>(fb, orow, wres4, lane, acc0, acc1); break;
        default: gather_core<8>(fb, orow, wres4, lane, acc0, acc1); break;
    }

    uint4* fo4 = (uint4*)(g_fout + (size_t)n * (N_TYPES * HID));
    fo4[lane] = make_uint4(f2tf32(acc0.x), f2tf32(acc0.y),
                           f2tf32(acc0.z), f2tf32(acc0.w));
    fo4[HID / 4 + lane] = make_uint4(f2tf32(acc1.x), f2tf32(acc1.y),
                                     f2tf32(acc1.z), f2tf32(acc1.w));
}

// ============================================================================
extern "C" void kernel_launch(void* const* d_in, const int* in_sizes, int n_in,
                              void* d_out, int out_size)
{
    const float* input_x    = (const float*)d_in[0];
    const int*   paths      = (const int*)d_in[1];
    const int*   ptypes     = (const int*)d_in[2];
    const float* fc_in_w    = (const float*)d_in[3];
    const float* fc_in_b    = (const float*)d_in[4];
    const float* fc_out_w   = (const float*)d_in[5];
    const float* fc_out_b   = (const float*)d_in[6];
    const float* layer_fc_w = (const float*)d_in[7];
    const float* path_w     = (const float*)d_in[8];
    float* out = (float*)d_out;

    constexpr int LDS_ = 36, NST = 3;
    constexpr size_t SM_128 = (size_t)NST * (64 * LDS_ + 128 * LDS_) * 4;
    constexpr size_t SM_64  = (size_t)NST * (64 * LDS_ + 64 * LDS_) * 4;

    static bool attr_done = false;
    if (!attr_done) {
        cudaFuncSetAttribute(gemm_tc_kernel<IN_DIM, HID, 0, true>,
                             cudaFuncAttributeMaxDynamicSharedMemorySize, SM_128);
        cudaFuncSetAttribute(gemm_tc_kernel<N_TYPES * HID, HID, 1, false>,
                             cudaFuncAttributeMaxDynamicSharedMemorySize, SM_128);
        cudaFuncSetAttribute(gemm_tc_kernel<HID, OUT_DIM, 0, true>,
                             cudaFuncAttributeMaxDynamicSharedMemorySize, SM_64);
        attr_done = true;
    }

    float *in_feats_p, *bufA_p, *bufB_p;
    uint32_t *fout_p, *w_in_p, *w_layer_p, *w_out_p;
    cudaGetSymbolAddress((void**)&in_feats_p, g_in_feats);
    cudaGetSymbolAddress((void**)&bufA_p, g_bufA);
    cudaGetSymbolAddress((void**)&bufB_p, g_bufB);
    cudaGetSymbolAddress((void**)&fout_p, g_fout);
    cudaGetSymbolAddress((void**)&w_in_p, g_w_in);
    cudaGetSymbolAddress((void**)&w_layer_p, g_w_layer);
    cudaGetSymbolAddress((void**)&w_out_p, g_w_out);

    const dim3 blk(256);
    const dim3 ggrd((N_NODES + 63) / 64);

    resolve_all_w_kernel<<<(N_LAYERS * N_TYPES * PATH_LEN * HID + 255) / 256,
                           blk>>>(path_w, ptypes);
    convert_w_kernel<<<(W_LAYER_ELEMS + 255) / 256, blk>>>(
        fc_in_w, layer_fc_w, fc_out_w);

    gemm_tc_kernel<IN_DIM, HID, 0, true><<<ggrd, blk, SM_128>>>(
        input_x, w_in_p, fc_in_b, nullptr, nullptr, in_feats_p);

    int cur = 0;  // feats = g_in_feats
    float* bufs[3] = {in_feats_p, bufA_p, bufB_p};
    for (int i = 0; i < N_LAYERS; i++) {
        gather_kernel<<<N_NODES / 8, blk>>>(paths, ptypes, cur, i);
        int nxt = (cur == 1) ? 2 : 1;
        gemm_tc_kernel<N_TYPES * HID, HID, 1, false><<<ggrd, blk, SM_128>>>(
            fout_p, w_layer_p + (size_t)i * HID * (N_TYPES * HID), nullptr,
            bufs[cur], in_feats_p, bufs[nxt]);
        cur = nxt;
    }

    gemm_tc_kernel<HID, OUT_DIM, 0, true><<<ggrd, blk, SM_64>>>(
        bufs[cur], w_out_p, fc_out_b, nullptr, nullptr, out);
}

// round 10
// speedup vs baseline: 1.7088x; 1.2554x over previous
#include <cuda_runtime.h>
#include <cuda_fp16.h>
#include <cstdint>

#define N_NODES 20000
#define IN_DIM 256
#define HID 128
#define OUT_DIM 64
#define N_LAYERS 4
#define N_PATHS 8
#define PATH_LEN 8
#define N_TYPES 2

// -------- scratch (no allocations allowed; device globals) --------
__device__ __half   g_in_feats[N_NODES * HID];
__device__ __half   g_bufA[N_NODES * HID];
__device__ __half   g_bufB[N_NODES * HID];
__device__ uint32_t g_fout[N_NODES * N_TYPES * HID];          // tf32 bits
__device__ float    g_wres[N_LAYERS * N_TYPES * PATH_LEN * HID];

// pre-converted tf32 weights
#define W_IN_ELEMS    (HID * IN_DIM)
#define W_LAYER_ELEMS (N_LAYERS * HID * N_TYPES * HID)
#define W_OUT_ELEMS   (OUT_DIM * HID)
__device__ uint32_t g_w_in[W_IN_ELEMS];
__device__ uint32_t g_w_layer[W_LAYER_ELEMS];
__device__ uint32_t g_w_out[W_OUT_ELEMS];

__device__ __forceinline__ uint32_t f2tf32(float f) {
    uint32_t u;
    asm("cvt.rna.tf32.f32 %0, %1;" : "=r"(u) : "f"(f));
    return u;
}

__device__ __forceinline__ void mma_tf32(
    float& d0, float& d1, float& d2, float& d3,
    uint32_t a0, uint32_t a1, uint32_t a2, uint32_t a3,
    uint32_t b0, uint32_t b1)
{
    asm volatile(
        "mma.sync.aligned.m16n8k8.row.col.f32.tf32.tf32.f32 "
        "{%0,%1,%2,%3}, {%4,%5,%6,%7}, {%8,%9}, {%0,%1,%2,%3};\n"
        : "+f"(d0), "+f"(d1), "+f"(d2), "+f"(d3)
        : "r"(a0), "r"(a1), "r"(a2), "r"(a3), "r"(b0), "r"(b1));
}

__device__ __forceinline__ void cp_async16(void* smem_dst, const void* gsrc,
                                           int src_bytes) {
    uint32_t s = (uint32_t)__cvta_generic_to_shared(smem_dst);
    asm volatile("cp.async.cg.shared.global [%0], [%1], 16, %2;\n"
                 :: "r"(s), "l"(gsrc), "r"(src_bytes));
}
__device__ __forceinline__ void cp_async_commit() {
    asm volatile("cp.async.commit_group;\n");
}
template <int N>
__device__ __forceinline__ void cp_async_wait() {
    asm volatile("cp.async.wait_group %0;\n" :: "n"(N));
}

__device__ __forceinline__ float4 h4_to_f4(uint2 u) {
    __half2 h0 = *reinterpret_cast<__half2*>(&u.x);
    __half2 h1 = *reinterpret_cast<__half2*>(&u.y);
    float2 a = __half22float2(h0);
    float2 b = __half22float2(h1);
    return make_float4(a.x, a.y, b.x, b.y);
}

// ============================================================================
// Prep kernels
// ============================================================================
__global__ void resolve_all_w_kernel(const float* __restrict__ pw,
                                     const int* __restrict__ ptypes)
{
    int i = blockIdx.x * blockDim.x + threadIdx.x;
    if (i >= N_LAYERS * N_TYPES * PATH_LEN * HID) return;
    int t = (i / (PATH_LEN * HID)) % N_TYPES;
    int cnt = 0;
#pragma unroll
    for (int p = 0; p < N_PATHS; p++) cnt += (__ldg(ptypes + p) == t);
    float inv = cnt > 0 ? 1.0f / (float)cnt : 0.0f;
    g_wres[i] = __ldg(pw + i) * inv;
}

__global__ void convert_w_kernel(const float* __restrict__ w_in,
                                 const float* __restrict__ w_layer,
                                 const float* __restrict__ w_out)
{
    int i = blockIdx.x * blockDim.x + threadIdx.x;
    if (i < W_IN_ELEMS)    g_w_in[i]    = f2tf32(__ldg(w_in + i));
    if (i < W_LAYER_ELEMS) g_w_layer[i] = f2tf32(__ldg(w_layer + i));
    if (i < W_OUT_ELEMS)   g_w_out[i]   = f2tf32(__ldg(w_out + i));
}

// ============================================================================
// TF32 tensor-core GEMM, 3-stage cp.async pipeline.
//   C[M, BN] = EPI( A[M, KDIM] @ W[BN, KDIM]^T ),  W already tf32 bits.
//   EPI==0: relu(acc + bias[n]);  EPI==1: 0.8*relu(acc)+0.1*pre+0.1*inf
//   AT: 0 = A is tf32 bits, 1 = A is fp32 (cvt at frag load), 2 = A is fp16.
//   OUTH: store C (and read pre/inf) as __half; else fp32.
// Block tile 64 x BN, 256 threads: 2 warps M x 4 warps N.
// ============================================================================
template <int KDIM, int BN, int EPI, int AT, bool OUTH>
__global__ void __launch_bounds__(256, 2)
gemm_tc_kernel(const void* __restrict__ Araw, const uint32_t* __restrict__ W,
               const float* __restrict__ bias, const void* __restrict__ pre,
               const void* __restrict__ inf, void* __restrict__ C)
{
    constexpr int BM = 64, BK = 32, LDS_ = 36, LDSH = 40, NST = 3;
    constexpr int NTW = BN / 32;
    constexpr int ABYTES = (AT == 2) ? BM * LDSH * 2 : BM * LDS_ * 4;
    constexpr int BSZ = BN * LDS_;
    constexpr int KTILES = KDIM / BK;
    constexpr int NCA = (AT == 2) ? (BM * BK * 2 / 16) / 256
                                  : (BM * BK * 4 / 16) / 256;
    constexpr int NCB = (BN * BK / 4) / 256;

    extern __shared__ unsigned char smraw[];
    uint32_t* Bs = (uint32_t*)(smraw + NST * ABYTES);

    const int tid    = threadIdx.x;
    const int lane   = tid & 31;
    const int warp   = tid >> 5;
    const int warp_m = warp & 1;
    const int warp_n = warp >> 1;
    const int gid    = lane >> 2;
    const int tig    = lane & 3;
    const int m0     = blockIdx.x * BM;

    float acc[2][NTW][4];
#pragma unroll
    for (int mt = 0; mt < 2; mt++)
#pragma unroll
        for (int nt = 0; nt < NTW; nt++)
#pragma unroll
            for (int r = 0; r < 4; r++) acc[mt][nt][r] = 0.f;

    auto issue = [&](int kt, int b) {
        if constexpr (AT == 2) {
            const __half* Ah = (const __half*)Araw;
#pragma unroll
            for (int i = 0; i < NCA; i++) {
                int c    = tid + i * 256;
                int row  = c >> 2, colh = (c & 3) << 3;   // 8 halves / chunk
                int ok   = (m0 + row) < N_NODES ? 16 : 0;
                cp_async16(smraw + b * ABYTES + (row * LDSH + colh) * 2,
                           Ah + (size_t)(m0 + row) * KDIM + kt * BK + colh, ok);
            }
        } else {
            const uint32_t* A = (const uint32_t*)Araw;
#pragma unroll
            for (int i = 0; i < NCA; i++) {
                int c   = tid + i * 256;
                int row = c >> 3, col = (c & 7) << 2;
                int ok  = (m0 + row) < N_NODES ? 16 : 0;
                cp_async16(smraw + b * ABYTES + (row * LDS_ + col) * 4,
                           A + (size_t)(m0 + row) * KDIM + kt * BK + col, ok);
            }
        }
#pragma unroll
        for (int i = 0; i < NCB; i++) {
            int c   = tid + i * 256;
            int row = c >> 3, col = (c & 7) << 2;
            cp_async16(Bs + b * BSZ + row * LDS_ + col,
                       W + (size_t)row * KDIM + kt * BK + col, 16);
        }
    };

#pragma unroll
    for (int s = 0; s < NST - 1; s++) {
        if (s < KTILES) issue(s, s);
        cp_async_commit();
    }

    for (int kt = 0; kt < KTILES; kt++) {
        if (kt + NST - 1 < KTILES) issue(kt + NST - 1, (kt + NST - 1) % NST);
        cp_async_commit();
        cp_async_wait<NST - 1>();
        __syncthreads();

        const unsigned char* Abase = smraw + (kt % NST) * ABYTES;
        const uint32_t* Bb = Bs + (kt % NST) * BSZ;
#pragma unroll
        for (int kk = 0; kk < BK / 8; kk++) {
            const int kb = kk * 8;
            uint32_t a[2][4];
#pragma unroll
            for (int mt = 0; mt < 2; mt++) {
                int r = warp_m * 32 + mt * 16 + gid;
                if constexpr (AT == 2) {
                    const __half* Ah = (const __half*)Abase;
                    a[mt][0] = f2tf32(__half2float(Ah[r * LDSH + kb + tig]));
                    a[mt][1] = f2tf32(__half2float(Ah[(r + 8) * LDSH + kb + tig]));
                    a[mt][2] = f2tf32(__half2float(Ah[r * LDSH + kb + tig + 4]));
                    a[mt][3] = f2tf32(__half2float(Ah[(r + 8) * LDSH + kb + tig + 4]));
                } else {
                    const uint32_t* Ab = (const uint32_t*)Abase;
                    a[mt][0] = Ab[r * LDS_ + kb + tig];
                    a[mt][1] = Ab[(r + 8) * LDS_ + kb + tig];
                    a[mt][2] = Ab[r * LDS_ + kb + tig + 4];
                    a[mt][3] = Ab[(r + 8) * LDS_ + kb + tig + 4];
                    if constexpr (AT == 1) {
#pragma unroll
                        for (int j = 0; j < 4; j++)
                            a[mt][j] = f2tf32(__uint_as_float(a[mt][j]));
                    }
                }
            }
            uint32_t b[NTW][2];
#pragma unroll
            for (int nt = 0; nt < NTW; nt++) {
                int c = warp_n * (NTW * 8) + nt * 8 + gid;
                b[nt][0] = Bb[c * LDS_ + kb + tig];
                b[nt][1] = Bb[c * LDS_ + kb + tig + 4];
            }
#pragma unroll
            for (int mt = 0; mt < 2; mt++)
#pragma unroll
                for (int nt = 0; nt < NTW; nt++)
                    mma_tf32(acc[mt][nt][0], acc[mt][nt][1],
                             acc[mt][nt][2], acc[mt][nt][3],
                             a[mt][0], a[mt][1], a[mt][2], a[mt][3],
                             b[nt][0], b[nt][1]);
        }
        __syncthreads();
    }

    // ---- epilogue ----
#pragma unroll
    for (int mt = 0; mt < 2; mt++) {
#pragma unroll
        for (int half = 0; half < 2; half++) {
            int row = m0 + warp_m * 32 + mt * 16 + half * 8 + gid;
            if (row >= N_NODES) continue;
#pragma unroll
            for (int nt = 0; nt < NTW; nt++) {
                int col = warp_n * (NTW * 8) + nt * 8 + 2 * tig;
                float v0 = acc[mt][nt][half * 2 + 0];
                float v1 = acc[mt][nt][half * 2 + 1];
                size_t off = (size_t)row * BN + col;
                if constexpr (EPI == 0) {
                    v0 = fmaxf(v0 + bias[col], 0.f);
                    v1 = fmaxf(v1 + bias[col + 1], 0.f);
                } else {
                    float2 p2, f2;
                    if constexpr (OUTH) {
                        p2 = __half22float2(*(const __half2*)((const __half*)pre + off));
                        f2 = __half22float2(*(const __half2*)((const __half*)inf + off));
                    } else {
                        p2 = *(const float2*)((const float*)pre + off);
                        f2 = *(const float2*)((const float*)inf + off);
                    }
                    v0 = 0.8f * fmaxf(v0, 0.f) + 0.1f * p2.x + 0.1f * f2.x;
                    v1 = 0.8f * fmaxf(v1, 0.f) + 0.1f * p2.y + 0.1f * f2.y;
                }
                if constexpr (OUTH) {
                    *(__half2*)((__half*)C + off) = __floats2half2_rn(v0, v1);
                } else {
                    *(float2*)((float*)C + off) = make_float2(v0, v1);
                }
            }
        }
    }
}

// ============================================================================
// Gather, l-outer factored form, fp16 feats:
//   acc_t = sum_l wres[t][l] * (sum_{p of type t} feats[idx[p,l]])
// 1 warp per node, 8 nodes per 256-thread block. Lane covers 4 h via 8B load.
// ============================================================================
__device__ __forceinline__ __half* buf_ptr(int s) {
    return s == 0 ? g_in_feats : (s == 1 ? g_bufA : g_bufB);
}

template <int C0>
__device__ __forceinline__ void gather_core(
    const uint2* __restrict__ fb, const int* __restrict__ orow,
    const float4* __restrict__ wres4, int lane,
    float4& acc0, float4& acc1)
{
#pragma unroll
    for (int l = 0; l < PATH_LEN; l++) {
        int4 o0 = *(const int4*)(orow + l * N_PATHS);
        int4 o1 = *(const int4*)(orow + l * N_PATHS + 4);
        float4 f0 = h4_to_f4(__ldg(fb + o0.x)), f1 = h4_to_f4(__ldg(fb + o0.y));
        float4 f2 = h4_to_f4(__ldg(fb + o0.z)), f3 = h4_to_f4(__ldg(fb + o0.w));
        float4 f4 = h4_to_f4(__ldg(fb + o1.x)), f5 = h4_to_f4(__ldg(fb + o1.y));
        float4 f6 = h4_to_f4(__ldg(fb + o1.z)), f7 = h4_to_f4(__ldg(fb + o1.w));
        float4 w0 = __ldg(wres4 + (size_t)l * (HID / 4) + lane);
        float4 w1 = __ldg(wres4 + (size_t)(PATH_LEN + l) * (HID / 4) + lane);

        float4 s0 = make_float4(0.f, 0.f, 0.f, 0.f);
        float4 s1 = make_float4(0.f, 0.f, 0.f, 0.f);
#define PUT(I, F) \
        if constexpr (I < C0) { s0.x += F.x; s0.y += F.y; s0.z += F.z; s0.w += F.w; } \
        else                  { s1.x += F.x; s1.y += F.y; s1.z += F.z; s1.w += F.w; }
        PUT(0, f0) PUT(1, f1) PUT(2, f2) PUT(3, f3)
        PUT(4, f4) PUT(5, f5) PUT(6, f6) PUT(7, f7)
#undef PUT
        acc0.x = fmaf(s0.x, w0.x, acc0.x);
        acc0.y = fmaf(s0.y, w0.y, acc0.y);
        acc0.z = fmaf(s0.z, w0.z, acc0.z);
        acc0.w = fmaf(s0.w, w0.w, acc0.w);
        acc1.x = fmaf(s1.x, w1.x, acc1.x);
        acc1.y = fmaf(s1.y, w1.y, acc1.y);
        acc1.z = fmaf(s1.z, w1.z, acc1.z);
        acc1.w = fmaf(s1.w, w1.w, acc1.w);
    }
}

__global__ void __launch_bounds__(256, 4)
gather_kernel(const int* __restrict__ paths, const int* __restrict__ ptypes,
              int feats_sel, int layer)
{
    const uint2* __restrict__ feats2 = (const uint2*)buf_ptr(feats_sel);
    const float4* __restrict__ wres4 =
        (const float4*)(g_wres + (size_t)layer * N_TYPES * PATH_LEN * HID);

    __shared__ int off_s[8][N_PATHS * PATH_LEN];   // [slot][l*8 + pos]
    __shared__ int types_s[N_PATHS];

    const int tid  = threadIdx.x;
    const int slot = tid >> 5;
    const int lane = tid & 31;
    const int n    = blockIdx.x * 8 + slot;

    if (tid < N_PATHS) types_s[tid] = ptypes[tid];
    __syncthreads();

    unsigned tmask = 0;
#pragma unroll
    for (int p = 0; p < N_PATHS; p++)
        tmask |= (types_s[p] ? 1u : 0u) << p;
    const int c0 = N_PATHS - __popc(tmask);

    // fill l-major, type-permuted offsets in uint2 (8B) units
    {
        int i  = tid * 2;
        int sl = i >> 6;
        int r  = i & 63;
        int p  = r >> 3, l = r & 7;
        int nn = blockIdx.x * 8 + sl;
        int2 v = *(const int2*)(paths + (size_t)p * (N_NODES * PATH_LEN)
                                + (size_t)nn * PATH_LEN + l);
        unsigned below = (1u << p) - 1u;
        int pos = (tmask >> p) & 1
                ? c0 + __popc(tmask & below)
                : __popc(~tmask & below & 0xFFu);
        off_s[sl][l * N_PATHS + pos]       = v.x * (HID / 4);
        off_s[sl][(l + 1) * N_PATHS + pos] = v.y * (HID / 4);
    }
    __syncthreads();

    const uint2* fb = feats2 + lane;
    const int* orow = off_s[slot];

    float4 acc0 = make_float4(0.f, 0.f, 0.f, 0.f);
    float4 acc1 = make_float4(0.f, 0.f, 0.f, 0.f);

    switch (c0) {
        case 0: gather_core<0>(fb, orow, wres4, lane, acc0, acc1); break;
        case 1: gather_core<1>(fb, orow, wres4, lane, acc0, acc1); break;
        case 2: gather_core<2>(fb, orow, wres4, lane, acc0, acc1); break;
        case 3: gather_core<3>(fb, orow, wres4, lane, acc0, acc1); break;
        case 4: gather_core<4>(fb, orow, wres4, lane, acc0, acc1); break;
        case 5: gather_core<5>(fb, orow, wres4, lane, acc0, acc1); break;
        case 6: gather_core<6>(fb, orow, wres4, lane, acc0, acc1); break;
        case 7: gather_core<7>(fb, orow, wres4, lane, acc0, acc1); break;
        default: gather_core<8>(fb, orow, wres4, lane, acc0, acc1); break;
    }

    uint4* fo4 = (uint4*)(g_fout + (size_t)n * (N_TYPES * HID));
    // lane covers h = 4*lane .. 4*lane+3
    fo4[lane] = make_uint4(f2tf32(acc0.x), f2tf32(acc0.y),
                           f2tf32(acc0.z), f2tf32(acc0.w));
    fo4[HID / 4 + lane] = make_uint4(f2tf32(acc1.x), f2tf32(acc1.y),
                                     f2tf32(acc1.z), f2tf32(acc1.w));
}

// ============================================================================
extern "C" void kernel_launch(void* const* d_in, const int* in_sizes, int n_in,
                              void* d_out, int out_size)
{
    const float* input_x    = (const float*)d_in[0];
    const int*   paths      = (const int*)d_in[1];
    const int*   ptypes     = (const int*)d_in[2];
    const float* fc_in_w    = (const float*)d_in[3];
    const float* fc_in_b    = (const float*)d_in[4];
    const float* fc_out_w   = (const float*)d_in[5];
    const float* fc_out_b   = (const float*)d_in[6];
    const float* layer_fc_w = (const float*)d_in[7];
    const float* path_w     = (const float*)d_in[8];
    float* out = (float*)d_out;

    constexpr int LDS_ = 36, LDSH = 40, NST = 3;
    constexpr size_t SM_IN    = (size_t)NST * (64 * LDS_ * 4 + 128 * LDS_ * 4);
    constexpr size_t SM_LAYER = SM_IN;
    constexpr size_t SM_OUT   = (size_t)NST * (64 * LDSH * 2 + 64 * LDS_ * 4);

    static bool attr_done = false;
    if (!attr_done) {
        cudaFuncSetAttribute(gemm_tc_kernel<IN_DIM, HID, 0, 1, true>,
                             cudaFuncAttributeMaxDynamicSharedMemorySize, SM_IN);
        cudaFuncSetAttribute(gemm_tc_kernel<N_TYPES * HID, HID, 1, 0, true>,
                             cudaFuncAttributeMaxDynamicSharedMemorySize, SM_LAYER);
        cudaFuncSetAttribute(gemm_tc_kernel<HID, OUT_DIM, 0, 2, false>,
                             cudaFuncAttributeMaxDynamicSharedMemorySize, SM_OUT);
        attr_done = true;
    }

    __half *in_feats_p, *bufA_p, *bufB_p;
    uint32_t *fout_p, *w_in_p, *w_layer_p, *w_out_p;
    cudaGetSymbolAddress((void**)&in_feats_p, g_in_feats);
    cudaGetSymbolAddress((void**)&bufA_p, g_bufA);
    cudaGetSymbolAddress((void**)&bufB_p, g_bufB);
    cudaGetSymbolAddress((void**)&fout_p, g_fout);
    cudaGetSymbolAddress((void**)&w_in_p, g_w_in);
    cudaGetSymbolAddress((void**)&w_layer_p, g_w_layer);
    cudaGetSymbolAddress((void**)&w_out_p, g_w_out);

    const dim3 blk(256);
    const dim3 ggrd((N_NODES + 63) / 64);

    resolve_all_w_kernel<<<(N_LAYERS * N_TYPES * PATH_LEN * HID + 255) / 256,
                           blk>>>(path_w, ptypes);
    convert_w_kernel<<<(W_LAYER_ELEMS + 255) / 256, blk>>>(
        fc_in_w, layer_fc_w, fc_out_w);

    gemm_tc_kernel<IN_DIM, HID, 0, 1, true><<<ggrd, blk, SM_IN>>>(
        input_x, w_in_p, fc_in_b, nullptr, nullptr, in_feats_p);

    int cur = 0;  // feats = g_in_feats
    __half* bufs[3] = {in_feats_p, bufA_p, bufB_p};
    for (int i = 0; i < N_LAYERS; i++) {
        gather_kernel<<<N_NODES / 8, blk>>>(paths, ptypes, cur, i);
        int nxt = (cur == 1) ? 2 : 1;
        gemm_tc_kernel<N_TYPES * HID, HID, 1, 0, true><<<ggrd, blk, SM_LAYER>>>(
            fout_p, w_layer_p + (size_t)i * HID * (N_TYPES * HID), nullptr,
            bufs[cur], in_feats_p, bufs[nxt]);
        cur = nxt;
    }

    gemm_tc_kernel<HID, OUT_DIM, 0, 2, false><<<ggrd, blk, SM_OUT>>>(
        bufs[cur], w_out_p, fc_out_b, nullptr, nullptr, out);
}

// round 11
// speedup vs baseline: 1.7581x; 1.0289x over previous
#include <cuda_runtime.h>
#include <cuda_fp16.h>
#include <cstdint>

#define N_NODES 20000
#define IN_DIM 256
#define HID 128
#define OUT_DIM 64
#define N_LAYERS 4
#define N_PATHS 8
#define PATH_LEN 8
#define N_TYPES 2

// -------- scratch (no allocations allowed; device globals) --------
__device__ __half   g_in_feats[N_NODES * HID];
__device__ __half   g_bufA[N_NODES * HID];
__device__ __half   g_bufB[N_NODES * HID];
__device__ uint32_t g_fout[N_NODES * N_TYPES * HID];          // tf32 bits
__device__ float    g_wres[N_LAYERS * N_TYPES * PATH_LEN * HID];

// pre-converted tf32 weights
#define W_IN_ELEMS    (HID * IN_DIM)
#define W_LAYER_ELEMS (N_LAYERS * HID * N_TYPES * HID)
#define W_OUT_ELEMS   (OUT_DIM * HID)
__device__ uint32_t g_w_in[W_IN_ELEMS];
__device__ uint32_t g_w_layer[W_LAYER_ELEMS];
__device__ uint32_t g_w_out[W_OUT_ELEMS];

__device__ __forceinline__ uint32_t f2tf32(float f) {
    uint32_t u;
    asm("cvt.rna.tf32.f32 %0, %1;" : "=r"(u) : "f"(f));
    return u;
}

__device__ __forceinline__ void mma_tf32(
    float& d0, float& d1, float& d2, float& d3,
    uint32_t a0, uint32_t a1, uint32_t a2, uint32_t a3,
    uint32_t b0, uint32_t b1)
{
    asm volatile(
        "mma.sync.aligned.m16n8k8.row.col.f32.tf32.tf32.f32 "
        "{%0,%1,%2,%3}, {%4,%5,%6,%7}, {%8,%9}, {%0,%1,%2,%3};\n"
        : "+f"(d0), "+f"(d1), "+f"(d2), "+f"(d3)
        : "r"(a0), "r"(a1), "r"(a2), "r"(a3), "r"(b0), "r"(b1));
}

__device__ __forceinline__ void cp_async16(void* smem_dst, const void* gsrc,
                                           int src_bytes) {
    uint32_t s = (uint32_t)__cvta_generic_to_shared(smem_dst);
    asm volatile("cp.async.cg.shared.global [%0], [%1], 16, %2;\n"
                 :: "r"(s), "l"(gsrc), "r"(src_bytes));
}
__device__ __forceinline__ void cp_async_commit() {
    asm volatile("cp.async.commit_group;\n");
}
template <int N>
__device__ __forceinline__ void cp_async_wait() {
    asm volatile("cp.async.wait_group %0;\n" :: "n"(N));
}

// ============================================================================
// Prep kernels
// ============================================================================
__global__ void resolve_all_w_kernel(const float* __restrict__ pw,
                                     const int* __restrict__ ptypes)
{
    int i = blockIdx.x * blockDim.x + threadIdx.x;
    if (i >= N_LAYERS * N_TYPES * PATH_LEN * HID) return;
    int t = (i / (PATH_LEN * HID)) % N_TYPES;
    int cnt = 0;
#pragma unroll
    for (int p = 0; p < N_PATHS; p++) cnt += (__ldg(ptypes + p) == t);
    float inv = cnt > 0 ? 1.0f / (float)cnt : 0.0f;
    g_wres[i] = __ldg(pw + i) * inv;
}

__global__ void convert_w_kernel(const float* __restrict__ w_in,
                                 const float* __restrict__ w_layer,
                                 const float* __restrict__ w_out)
{
    int i = blockIdx.x * blockDim.x + threadIdx.x;
    if (i < W_IN_ELEMS)    g_w_in[i]    = f2tf32(__ldg(w_in + i));
    if (i < W_LAYER_ELEMS) g_w_layer[i] = f2tf32(__ldg(w_layer + i));
    if (i < W_OUT_ELEMS)   g_w_out[i]   = f2tf32(__ldg(w_out + i));
}

// ============================================================================
// TF32 tensor-core GEMM, 3-stage cp.async pipeline.
//   C[M, BN] = EPI( A[M, KDIM] @ W[BN, KDIM]^T ),  W already tf32 bits.
//   EPI==0: relu(acc + bias[n]);  EPI==1: 0.8*relu(acc)+0.1*pre+0.1*inf
//   AT: 0 = A is tf32 bits, 1 = A is fp32 (cvt at frag load), 2 = A is fp16.
//   OUTH: store C (and read pre/inf) as __half; else fp32.
// Block tile 64 x BN, 256 threads: 2 warps M x 4 warps N.
// ============================================================================
template <int KDIM, int BN, int EPI, int AT, bool OUTH>
__global__ void __launch_bounds__(256, 2)
gemm_tc_kernel(const void* __restrict__ Araw, const uint32_t* __restrict__ W,
               const float* __restrict__ bias, const void* __restrict__ pre,
               const void* __restrict__ inf, void* __restrict__ C)
{
    constexpr int BM = 64, BK = 32, LDS_ = 36, LDSH = 40, NST = 3;
    constexpr int NTW = BN / 32;
    constexpr int ABYTES = (AT == 2) ? BM * LDSH * 2 : BM * LDS_ * 4;
    constexpr int BSZ = BN * LDS_;
    constexpr int KTILES = KDIM / BK;
    constexpr int NCA = (AT == 2) ? (BM * BK * 2 / 16) / 256
                                  : (BM * BK * 4 / 16) / 256;
    constexpr int NCB = (BN * BK / 4) / 256;

    extern __shared__ unsigned char smraw[];
    uint32_t* Bs = (uint32_t*)(smraw + NST * ABYTES);

    const int tid    = threadIdx.x;
    const int lane   = tid & 31;
    const int warp   = tid >> 5;
    const int warp_m = warp & 1;
    const int warp_n = warp >> 1;
    const int gid    = lane >> 2;
    const int tig    = lane & 3;
    const int m0     = blockIdx.x * BM;

    float acc[2][NTW][4];
#pragma unroll
    for (int mt = 0; mt < 2; mt++)
#pragma unroll
        for (int nt = 0; nt < NTW; nt++)
#pragma unroll
            for (int r = 0; r < 4; r++) acc[mt][nt][r] = 0.f;

    auto issue = [&](int kt, int b) {
        if constexpr (AT == 2) {
            const __half* Ah = (const __half*)Araw;
#pragma unroll
            for (int i = 0; i < NCA; i++) {
                int c    = tid + i * 256;
                int row  = c >> 2, colh = (c & 3) << 3;
                int ok   = (m0 + row) < N_NODES ? 16 : 0;
                cp_async16(smraw + b * ABYTES + (row * LDSH + colh) * 2,
                           Ah + (size_t)(m0 + row) * KDIM + kt * BK + colh, ok);
            }
        } else {
            const uint32_t* A = (const uint32_t*)Araw;
#pragma unroll
            for (int i = 0; i < NCA; i++) {
                int c   = tid + i * 256;
                int row = c >> 3, col = (c & 7) << 2;
                int ok  = (m0 + row) < N_NODES ? 16 : 0;
                cp_async16(smraw + b * ABYTES + (row * LDS_ + col) * 4,
                           A + (size_t)(m0 + row) * KDIM + kt * BK + col, ok);
            }
        }
#pragma unroll
        for (int i = 0; i < NCB; i++) {
            int c   = tid + i * 256;
            int row = c >> 3, col = (c & 7) << 2;
            cp_async16(Bs + b * BSZ + row * LDS_ + col,
                       W + (size_t)row * KDIM + kt * BK + col, 16);
        }
    };

#pragma unroll
    for (int s = 0; s < NST - 1; s++) {
        if (s < KTILES) issue(s, s);
        cp_async_commit();
    }

    for (int kt = 0; kt < KTILES; kt++) {
        if (kt + NST - 1 < KTILES) issue(kt + NST - 1, (kt + NST - 1) % NST);
        cp_async_commit();
        cp_async_wait<NST - 1>();
        __syncthreads();

        const unsigned char* Abase = smraw + (kt % NST) * ABYTES;
        const uint32_t* Bb = Bs + (kt % NST) * BSZ;
#pragma unroll
        for (int kk = 0; kk < BK / 8; kk++) {
            const int kb = kk * 8;
            uint32_t a[2][4];
#pragma unroll
            for (int mt = 0; mt < 2; mt++) {
                int r = warp_m * 32 + mt * 16 + gid;
                if constexpr (AT == 2) {
                    const __half* Ah = (const __half*)Abase;
                    a[mt][0] = f2tf32(__half2float(Ah[r * LDSH + kb + tig]));
                    a[mt][1] = f2tf32(__half2float(Ah[(r + 8) * LDSH + kb + tig]));
                    a[mt][2] = f2tf32(__half2float(Ah[r * LDSH + kb + tig + 4]));
                    a[mt][3] = f2tf32(__half2float(Ah[(r + 8) * LDSH + kb + tig + 4]));
                } else {
                    const uint32_t* Ab = (const uint32_t*)Abase;
                    a[mt][0] = Ab[r * LDS_ + kb + tig];
                    a[mt][1] = Ab[(r + 8) * LDS_ + kb + tig];
                    a[mt][2] = Ab[r * LDS_ + kb + tig + 4];
                    a[mt][3] = Ab[(r + 8) * LDS_ + kb + tig + 4];
                    if constexpr (AT == 1) {
#pragma unroll
                        for (int j = 0; j < 4; j++)
                            a[mt][j] = f2tf32(__uint_as_float(a[mt][j]));
                    }
                }
            }
            uint32_t b[NTW][2];
#pragma unroll
            for (int nt = 0; nt < NTW; nt++) {
                int c = warp_n * (NTW * 8) + nt * 8 + gid;
                b[nt][0] = Bb[c * LDS_ + kb + tig];
                b[nt][1] = Bb[c * LDS_ + kb + tig + 4];
            }
#pragma unroll
            for (int mt = 0; mt < 2; mt++)
#pragma unroll
                for (int nt = 0; nt < NTW; nt++)
                    mma_tf32(acc[mt][nt][0], acc[mt][nt][1],
                             acc[mt][nt][2], acc[mt][nt][3],
                             a[mt][0], a[mt][1], a[mt][2], a[mt][3],
                             b[nt][0], b[nt][1]);
        }
        __syncthreads();
    }

    // ---- epilogue ----
#pragma unroll
    for (int mt = 0; mt < 2; mt++) {
#pragma unroll
        for (int half = 0; half < 2; half++) {
            int row = m0 + warp_m * 32 + mt * 16 + half * 8 + gid;
            if (row >= N_NODES) continue;
#pragma unroll
            for (int nt = 0; nt < NTW; nt++) {
                int col = warp_n * (NTW * 8) + nt * 8 + 2 * tig;
                float v0 = acc[mt][nt][half * 2 + 0];
                float v1 = acc[mt][nt][half * 2 + 1];
                size_t off = (size_t)row * BN + col;
                if constexpr (EPI == 0) {
                    v0 = fmaxf(v0 + bias[col], 0.f);
                    v1 = fmaxf(v1 + bias[col + 1], 0.f);
                } else {
                    float2 p2, f2;
                    if constexpr (OUTH) {
                        p2 = __half22float2(*(const __half2*)((const __half*)pre + off));
                        f2 = __half22float2(*(const __half2*)((const __half*)inf + off));
                    } else {
                        p2 = *(const float2*)((const float*)pre + off);
                        f2 = *(const float2*)((const float*)inf + off);
                    }
                    v0 = 0.8f * fmaxf(v0, 0.f) + 0.1f * p2.x + 0.1f * f2.x;
                    v1 = 0.8f * fmaxf(v1, 0.f) + 0.1f * p2.y + 0.1f * f2.y;
                }
                if constexpr (OUTH) {
                    *(__half2*)((__half*)C + off) = __floats2half2_rn(v0, v1);
                } else {
                    *(float2*)((float*)C + off) = make_float2(v0, v1);
                }
            }
        }
    }
}

// ============================================================================
// Gather, l-outer factored form, fp16 feats, half2 pairwise-tree path-sum:
//   acc_t = sum_l wres[t][l] * float( treesum_{p of type t} feats_h[idx[p,l]] )
// 1 warp per node, 8 nodes per 256-thread block.
// ============================================================================
__device__ __forceinline__ __half* buf_ptr(int s) {
    return s == 0 ? g_in_feats : (s == 1 ? g_bufA : g_bufB);
}

// pairwise tree sum of v[BEG..END) (END > BEG)
template <int BEG, int END>
__device__ __forceinline__ __half2 tree2(const __half2* v) {
    if constexpr (END - BEG == 1) {
        return v[BEG];
    } else {
        constexpr int MID = (BEG + END) / 2;
        return __hadd2(tree2<BEG, MID>(v), tree2<MID, END>(v));
    }
}

template <int C0>
__device__ __forceinline__ void gather_core(
    const uint2* __restrict__ fb, const int* __restrict__ orow,
    const float4* __restrict__ wres4, int lane,
    float4& acc0, float4& acc1)
{
#pragma unroll
    for (int l = 0; l < PATH_LEN; l++) {
        int4 o0 = *(const int4*)(orow + l * N_PATHS);
        int4 o1 = *(const int4*)(orow + l * N_PATHS + 4);
        uint2 r[8];
        r[0] = __ldg(fb + o0.x); r[1] = __ldg(fb + o0.y);
        r[2] = __ldg(fb + o0.z); r[3] = __ldg(fb + o0.w);
        r[4] = __ldg(fb + o1.x); r[5] = __ldg(fb + o1.y);
        r[6] = __ldg(fb + o1.z); r[7] = __ldg(fb + o1.w);

        __half2 va[8], vb[8];
#pragma unroll
        for (int i = 0; i < 8; i++) {
            va[i] = *reinterpret_cast<__half2*>(&r[i].x);
            vb[i] = *reinterpret_cast<__half2*>(&r[i].y);
        }

        float4 w0 = __ldg(wres4 + (size_t)l * (HID / 4) + lane);
        float4 w1 = __ldg(wres4 + (size_t)(PATH_LEN + l) * (HID / 4) + lane);

        if constexpr (C0 > 0) {
            __half2 sa = tree2<0, C0>(va);
            __half2 sb = tree2<0, C0>(vb);
            float2 fa = __half22float2(sa);
            float2 fbv = __half22float2(sb);
            acc0.x = fmaf(fa.x,  w0.x, acc0.x);
            acc0.y = fmaf(fa.y,  w0.y, acc0.y);
            acc0.z = fmaf(fbv.x, w0.z, acc0.z);
            acc0.w = fmaf(fbv.y, w0.w, acc0.w);
        }
        if constexpr (C0 < N_PATHS) {
            __half2 sa = tree2<C0, N_PATHS>(va);
            __half2 sb = tree2<C0, N_PATHS>(vb);
            float2 fa = __half22float2(sa);
            float2 fbv = __half22float2(sb);
            acc1.x = fmaf(fa.x,  w1.x, acc1.x);
            acc1.y = fmaf(fa.y,  w1.y, acc1.y);
            acc1.z = fmaf(fbv.x, w1.z, acc1.z);
            acc1.w = fmaf(fbv.y, w1.w, acc1.w);
        }
    }
}

__global__ void __launch_bounds__(256, 4)
gather_kernel(const int* __restrict__ paths, const int* __restrict__ ptypes,
              int feats_sel, int layer)
{
    const uint2* __restrict__ feats2 = (const uint2*)buf_ptr(feats_sel);
    const float4* __restrict__ wres4 =
        (const float4*)(g_wres + (size_t)layer * N_TYPES * PATH_LEN * HID);

    __shared__ int off_s[8][N_PATHS * PATH_LEN];   // [slot][l*8 + pos]
    __shared__ int types_s[N_PATHS];

    const int tid  = threadIdx.x;
    const int slot = tid >> 5;
    const int lane = tid & 31;
    const int n    = blockIdx.x * 8 + slot;

    if (tid < N_PATHS) types_s[tid] = ptypes[tid];
    __syncthreads();

    unsigned tmask = 0;
#pragma unroll
    for (int p = 0; p < N_PATHS; p++)
        tmask |= (types_s[p] ? 1u : 0u) << p;
    const int c0 = N_PATHS - __popc(tmask);

    // fill l-major, type-permuted offsets in uint2 (8B) units
    {
        int i  = tid * 2;
        int sl = i >> 6;
        int r  = i & 63;
        int p  = r >> 3, l = r & 7;
        int nn = blockIdx.x * 8 + sl;
        int2 v = *(const int2*)(paths + (size_t)p * (N_NODES * PATH_LEN)
                                + (size_t)nn * PATH_LEN + l);
        unsigned below = (1u << p) - 1u;
        int pos = (tmask >> p) & 1
                ? c0 + __popc(tmask & below)
                : __popc(~tmask & below & 0xFFu);
        off_s[sl][l * N_PATHS + pos]       = v.x * (HID / 4);
        off_s[sl][(l + 1) * N_PATHS + pos] = v.y * (HID / 4);
    }
    __syncthreads();

    const uint2* fb = feats2 + lane;
    const int* orow = off_s[slot];

    float4 acc0 = make_float4(0.f, 0.f, 0.f, 0.f);
    float4 acc1 = make_float4(0.f, 0.f, 0.f, 0.f);

    switch (c0) {
        case 0: gather_core<0>(fb, orow, wres4, lane, acc0, acc1); break;
        case 1: gather_core<1>(fb, orow, wres4, lane, acc0, acc1); break;
        case 2: gather_core<2>(fb, orow, wres4, lane, acc0, acc1); break;
        case 3: gather_core<3>(fb, orow, wres4, lane, acc0, acc1); break;
        case 4: gather_core<4>(fb, orow, wres4, lane, acc0, acc1); break;
        case 5: gather_core<5>(fb, orow, wres4, lane, acc0, acc1); break;
        case 6: gather_core<6>(fb, orow, wres4, lane, acc0, acc1); break;
        case 7: gather_core<7>(fb, orow, wres4, lane, acc0, acc1); break;
        default: gather_core<8>(fb, orow, wres4, lane, acc0, acc1); break;
    }

    uint4* fo4 = (uint4*)(g_fout + (size_t)n * (N_TYPES * HID));
    fo4[lane] = make_uint4(f2tf32(acc0.x), f2tf32(acc0.y),
                           f2tf32(acc0.z), f2tf32(acc0.w));
    fo4[HID / 4 + lane] = make_uint4(f2tf32(acc1.x), f2tf32(acc1.y),
                                     f2tf32(acc1.z), f2tf32(acc1.w));
}

// ============================================================================
extern "C" void kernel_launch(void* const* d_in, const int* in_sizes, int n_in,
                              void* d_out, int out_size)
{
    const float* input_x    = (const float*)d_in[0];
    const int*   paths      = (const int*)d_in[1];
    const int*   ptypes     = (const int*)d_in[2];
    const float* fc_in_w    = (const float*)d_in[3];
    const float* fc_in_b    = (const float*)d_in[4];
    const float* fc_out_w   = (const float*)d_in[5];
    const float* fc_out_b   = (const float*)d_in[6];
    const float* layer_fc_w = (const float*)d_in[7];
    const float* path_w     = (const float*)d_in[8];
    float* out = (float*)d_out;

    constexpr int LDS_ = 36, LDSH = 40, NST = 3;
    constexpr size_t SM_IN    = (size_t)NST * (64 * LDS_ * 4 + 128 * LDS_ * 4);
    constexpr size_t SM_LAYER = SM_IN;
    constexpr size_t SM_OUT   = (size_t)NST * (64 * LDSH * 2 + 64 * LDS_ * 4);

    static bool attr_done = false;
    if (!attr_done) {
        cudaFuncSetAttribute(gemm_tc_kernel<IN_DIM, HID, 0, 1, true>,
                             cudaFuncAttributeMaxDynamicSharedMemorySize, SM_IN);
        cudaFuncSetAttribute(gemm_tc_kernel<N_TYPES * HID, HID, 1, 0, true>,
                             cudaFuncAttributeMaxDynamicSharedMemorySize, SM_LAYER);
        cudaFuncSetAttribute(gemm_tc_kernel<HID, OUT_DIM, 0, 2, false>,
                             cudaFuncAttributeMaxDynamicSharedMemorySize, SM_OUT);
        attr_done = true;
    }

    __half *in_feats_p, *bufA_p, *bufB_p;
    uint32_t *fout_p, *w_in_p, *w_layer_p, *w_out_p;
    cudaGetSymbolAddress((void**)&in_feats_p, g_in_feats);
    cudaGetSymbolAddress((void**)&bufA_p, g_bufA);
    cudaGetSymbolAddress((void**)&bufB_p, g_bufB);
    cudaGetSymbolAddress((void**)&fout_p, g_fout);
    cudaGetSymbolAddress((void**)&w_in_p, g_w_in);
    cudaGetSymbolAddress((void**)&w_layer_p, g_w_layer);
    cudaGetSymbolAddress((void**)&w_out_p, g_w_out);

    const dim3 blk(256);
    const dim3 ggrd((N_NODES + 63) / 64);

    resolve_all_w_kernel<<<(N_LAYERS * N_TYPES * PATH_LEN * HID + 255) / 256,
                           blk>>>(path_w, ptypes);
    convert_w_kernel<<<(W_LAYER_ELEMS + 255) / 256, blk>>>(
        fc_in_w, layer_fc_w, fc_out_w);

    gemm_tc_kernel<IN_DIM, HID, 0, 1, true><<<ggrd, blk, SM_IN>>>(
        input_x, w_in_p, fc_in_b, nullptr, nullptr, in_feats_p);

    int cur = 0;  // feats = g_in_feats
    __half* bufs[3] = {in_feats_p, bufA_p, bufB_p};
    for (int i = 0; i < N_LAYERS; i++) {
        gather_kernel<<<N_NODES / 8, blk>>>(paths, ptypes, cur, i);
        int nxt = (cur == 1) ? 2 : 1;
        gemm_tc_kernel<N_TYPES * HID, HID, 1, 0, true><<<ggrd, blk, SM_LAYER>>>(
            fout_p, w_layer_p + (size_t)i * HID * (N_TYPES * HID), nullptr,
            bufs[cur], in_feats_p, bufs[nxt]);
        cur = nxt;
    }

    gemm_tc_kernel<HID, OUT_DIM, 0, 2, false><<<ggrd, blk, SM_OUT>>>(
        bufs[cur], w_out_p, fc_out_b, nullptr, nullptr, out);
}

// round 12
// speedup vs baseline: 1.9798x; 1.1261x over previous
#include <cuda_runtime.h>
#include <cuda_fp16.h>
#include <cstdint>

#define N_NODES 20000
#define IN_DIM 256
#define HID 128
#define OUT_DIM 64
#define N_LAYERS 4
#define N_PATHS 8
#define PATH_LEN 8
#define N_TYPES 2

// -------- scratch (no allocations allowed; device globals) --------
__device__ __half   g_in_feats[N_NODES * HID];
__device__ __half   g_bufA[N_NODES * HID];
__device__ __half   g_bufB[N_NODES * HID];
__device__ __half   g_fout[N_NODES * N_TYPES * HID];       // fp16 now
__device__ __half   g_x_h[N_NODES * IN_DIM];               // fp16 input
__device__ float    g_wres[N_LAYERS * N_TYPES * PATH_LEN * HID];

// pre-converted fp16 weights
#define W_IN_ELEMS    (HID * IN_DIM)
#define W_LAYER_ELEMS (N_LAYERS * HID * N_TYPES * HID)
#define W_OUT_ELEMS   (OUT_DIM * HID)
__device__ __half g_w_in[W_IN_ELEMS];
__device__ __half g_w_layer[W_LAYER_ELEMS];
__device__ __half g_w_out[W_OUT_ELEMS];

__device__ __forceinline__ void mma_f16(
    float& d0, float& d1, float& d2, float& d3,
    uint32_t a0, uint32_t a1, uint32_t a2, uint32_t a3,
    uint32_t b0, uint32_t b1)
{
    asm volatile(
        "mma.sync.aligned.m16n8k16.row.col.f32.f16.f16.f32 "
        "{%0,%1,%2,%3}, {%4,%5,%6,%7}, {%8,%9}, {%0,%1,%2,%3};\n"
        : "+f"(d0), "+f"(d1), "+f"(d2), "+f"(d3)
        : "r"(a0), "r"(a1), "r"(a2), "r"(a3), "r"(b0), "r"(b1));
}

__device__ __forceinline__ void cp_async16(void* smem_dst, const void* gsrc,
                                           int src_bytes) {
    uint32_t s = (uint32_t)__cvta_generic_to_shared(smem_dst);
    asm volatile("cp.async.cg.shared.global [%0], [%1], 16, %2;\n"
                 :: "r"(s), "l"(gsrc), "r"(src_bytes));
}
__device__ __forceinline__ void cp_async_commit() {
    asm volatile("cp.async.commit_group;\n");
}
template <int N>
__device__ __forceinline__ void cp_async_wait() {
    asm volatile("cp.async.wait_group %0;\n" :: "n"(N));
}

// ============================================================================
// Prep kernels
// ============================================================================
__global__ void resolve_all_w_kernel(const float* __restrict__ pw,
                                     const int* __restrict__ ptypes)
{
    int i = blockIdx.x * blockDim.x + threadIdx.x;
    if (i >= N_LAYERS * N_TYPES * PATH_LEN * HID) return;
    int t = (i / (PATH_LEN * HID)) % N_TYPES;
    int cnt = 0;
#pragma unroll
    for (int p = 0; p < N_PATHS; p++) cnt += (__ldg(ptypes + p) == t);
    float inv = cnt > 0 ? 1.0f / (float)cnt : 0.0f;
    g_wres[i] = __ldg(pw + i) * inv;
}

// converts input_x and all weights to fp16 (grid sized for the largest)
__global__ void convert_all_kernel(const float* __restrict__ x,
                                   const float* __restrict__ w_in,
                                   const float* __restrict__ w_layer,
                                   const float* __restrict__ w_out)
{
    int i = blockIdx.x * blockDim.x + threadIdx.x;
    if (i < N_NODES * IN_DIM) g_x_h[i]   = __float2half(__ldg(x + i));
    if (i < W_IN_ELEMS)       g_w_in[i]  = __float2half(__ldg(w_in + i));
    if (i < W_LAYER_ELEMS)    g_w_layer[i] = __float2half(__ldg(w_layer + i));
    if (i < W_OUT_ELEMS)      g_w_out[i] = __float2half(__ldg(w_out + i));
}

// ============================================================================
// FP16 tensor-core GEMM (m16n8k16, fp32 accum), 3-stage cp.async pipeline.
//   C[M, BN] = EPI( A[M, KDIM] @ W[BN, KDIM]^T ),  A and W are __half.
//   EPI==0: relu(acc + bias[n]);  EPI==1: 0.8*relu(acc)+0.1*pre+0.1*inf
//   OUTH: store C (and read pre/inf) as __half; else fp32.
// Block tile 64 x BN, 256 threads: 2 warps M x 4 warps N, warp 32 x (BN/4).
// ============================================================================
template <int KDIM, int BN, int EPI, bool OUTH>
__global__ void __launch_bounds__(256, 3)
gemm_h_kernel(const __half* __restrict__ A, const __half* __restrict__ W,
              const float* __restrict__ bias, const void* __restrict__ pre,
              const void* __restrict__ inf, void* __restrict__ C)
{
    constexpr int BM = 64, BK = 32, LDSH = 40, NST = 3;
    constexpr int NTW = BN / 32;
    constexpr int ASZ = BM * LDSH;                 // halves per A stage
    constexpr int BSZ = BN * LDSH;
    constexpr int KTILES = KDIM / BK;
    constexpr int NCA = (BM * BK) / 8 / 256;       // 16B chunks per thread (1)
    constexpr int NCB = (BN * BK) / 8 / 256;       // 2 for BN=128, 1 for 64

    extern __shared__ __half smh[];
    __half* As = smh;
    __half* Bs = smh + NST * ASZ;

    const int tid    = threadIdx.x;
    const int lane   = tid & 31;
    const int warp   = tid >> 5;
    const int warp_m = warp & 1;
    const int warp_n = warp >> 1;
    const int gid    = lane >> 2;
    const int tig    = lane & 3;
    const int m0     = blockIdx.x * BM;

    float acc[2][NTW][4];
#pragma unroll
    for (int mt = 0; mt < 2; mt++)
#pragma unroll
        for (int nt = 0; nt < NTW; nt++)
#pragma unroll
            for (int r = 0; r < 4; r++) acc[mt][nt][r] = 0.f;

    auto issue = [&](int kt, int b) {
#pragma unroll
        for (int i = 0; i < NCA; i++) {
            int c    = tid + i * 256;
            int row  = c >> 2, colh = (c & 3) << 3;    // 8 halves per chunk
            int ok   = (m0 + row) < N_NODES ? 16 : 0;
            cp_async16(As + b * ASZ + row * LDSH + colh,
                       A + (size_t)(m0 + row) * KDIM + kt * BK + colh, ok);
        }
#pragma unroll
        for (int i = 0; i < NCB; i++) {
            int c    = tid + i * 256;
            int row  = c >> 2, colh = (c & 3) << 3;
            cp_async16(Bs + b * BSZ + row * LDSH + colh,
                       W + (size_t)row * KDIM + kt * BK + colh, 16);
        }
    };

#pragma unroll
    for (int s = 0; s < NST - 1; s++) {
        if (s < KTILES) issue(s, s);
        cp_async_commit();
    }

    for (int kt = 0; kt < KTILES; kt++) {
        if (kt + NST - 1 < KTILES) issue(kt + NST - 1, (kt + NST - 1) % NST);
        cp_async_commit();
        cp_async_wait<NST - 1>();
        __syncthreads();

        const __half* Ab = As + (kt % NST) * ASZ;
        const __half* Bb = Bs + (kt % NST) * BSZ;
#pragma unroll
        for (int kk = 0; kk < BK / 16; kk++) {
            const int kb = kk * 16;
            uint32_t a[2][4];
#pragma unroll
            for (int mt = 0; mt < 2; mt++) {
                int r = warp_m * 32 + mt * 16 + gid;
                a[mt][0] = *(const uint32_t*)(Ab + r * LDSH + kb + 2 * tig);
                a[mt][1] = *(const uint32_t*)(Ab + (r + 8) * LDSH + kb + 2 * tig);
                a[mt][2] = *(const uint32_t*)(Ab + r * LDSH + kb + 8 + 2 * tig);
                a[mt][3] = *(const uint32_t*)(Ab + (r + 8) * LDSH + kb + 8 + 2 * tig);
            }
            uint32_t b[NTW][2];
#pragma unroll
            for (int nt = 0; nt < NTW; nt++) {
                int c = warp_n * (NTW * 8) + nt * 8 + gid;
                b[nt][0] = *(const uint32_t*)(Bb + c * LDSH + kb + 2 * tig);
                b[nt][1] = *(const uint32_t*)(Bb + c * LDSH + kb + 8 + 2 * tig);
            }
#pragma unroll
            for (int mt = 0; mt < 2; mt++)
#pragma unroll
                for (int nt = 0; nt < NTW; nt++)
                    mma_f16(acc[mt][nt][0], acc[mt][nt][1],
                            acc[mt][nt][2], acc[mt][nt][3],
                            a[mt][0], a[mt][1], a[mt][2], a[mt][3],
                            b[nt][0], b[nt][1]);
        }
        __syncthreads();
    }

    // ---- epilogue ----
#pragma unroll
    for (int mt = 0; mt < 2; mt++) {
#pragma unroll
        for (int half = 0; half < 2; half++) {
            int row = m0 + warp_m * 32 + mt * 16 + half * 8 + gid;
            if (row >= N_NODES) continue;
#pragma unroll
            for (int nt = 0; nt < NTW; nt++) {
                int col = warp_n * (NTW * 8) + nt * 8 + 2 * tig;
                float v0 = acc[mt][nt][half * 2 + 0];
                float v1 = acc[mt][nt][half * 2 + 1];
                size_t off = (size_t)row * BN + col;
                if constexpr (EPI == 0) {
                    v0 = fmaxf(v0 + bias[col], 0.f);
                    v1 = fmaxf(v1 + bias[col + 1], 0.f);
                } else {
                    float2 p2, f2;
                    if constexpr (OUTH) {
                        p2 = __half22float2(*(const __half2*)((const __half*)pre + off));
                        f2 = __half22float2(*(const __half2*)((const __half*)inf + off));
                    } else {
                        p2 = *(const float2*)((const float*)pre + off);
                        f2 = *(const float2*)((const float*)inf + off);
                    }
                    v0 = 0.8f * fmaxf(v0, 0.f) + 0.1f * p2.x + 0.1f * f2.x;
                    v1 = 0.8f * fmaxf(v1, 0.f) + 0.1f * p2.y + 0.1f * f2.y;
                }
                if constexpr (OUTH) {
                    *(__half2*)((__half*)C + off) = __floats2half2_rn(v0, v1);
                } else {
                    *(float2*)((float*)C + off) = make_float2(v0, v1);
                }
            }
        }
    }
}

// ============================================================================
// Gather, l-outer factored form, fp16 feats, half2 pairwise-tree path-sum.
// Writes fout as fp16. 1 warp per node, 8 nodes per 256-thread block.
// ============================================================================
__device__ __forceinline__ __half* buf_ptr(int s) {
    return s == 0 ? g_in_feats : (s == 1 ? g_bufA : g_bufB);
}

template <int BEG, int END>
__device__ __forceinline__ __half2 tree2(const __half2* v) {
    if constexpr (END - BEG == 1) {
        return v[BEG];
    } else {
        constexpr int MID = (BEG + END) / 2;
        return __hadd2(tree2<BEG, MID>(v), tree2<MID, END>(v));
    }
}

template <int C0>
__device__ __forceinline__ void gather_core(
    const uint2* __restrict__ fb, const int* __restrict__ orow,
    const float4* __restrict__ wres4, int lane,
    float4& acc0, float4& acc1)
{
#pragma unroll
    for (int l = 0; l < PATH_LEN; l++) {
        int4 o0 = *(const int4*)(orow + l * N_PATHS);
        int4 o1 = *(const int4*)(orow + l * N_PATHS + 4);
        uint2 r[8];
        r[0] = __ldg(fb + o0.x); r[1] = __ldg(fb + o0.y);
        r[2] = __ldg(fb + o0.z); r[3] = __ldg(fb + o0.w);
        r[4] = __ldg(fb + o1.x); r[5] = __ldg(fb + o1.y);
        r[6] = __ldg(fb + o1.z); r[7] = __ldg(fb + o1.w);

        __half2 va[8], vb[8];
#pragma unroll
        for (int i = 0; i < 8; i++) {
            va[i] = *reinterpret_cast<__half2*>(&r[i].x);
            vb[i] = *reinterpret_cast<__half2*>(&r[i].y);
        }

        float4 w0 = __ldg(wres4 + (size_t)l * (HID / 4) + lane);
        float4 w1 = __ldg(wres4 + (size_t)(PATH_LEN + l) * (HID / 4) + lane);

        if constexpr (C0 > 0) {
            __half2 sa = tree2<0, C0>(va);
            __half2 sb = tree2<0, C0>(vb);
            float2 fa = __half22float2(sa);
            float2 fbv = __half22float2(sb);
            acc0.x = fmaf(fa.x,  w0.x, acc0.x);
            acc0.y = fmaf(fa.y,  w0.y, acc0.y);
            acc0.z = fmaf(fbv.x, w0.z, acc0.z);
            acc0.w = fmaf(fbv.y, w0.w, acc0.w);
        }
        if constexpr (C0 < N_PATHS) {
            __half2 sa = tree2<C0, N_PATHS>(va);
            __half2 sb = tree2<C0, N_PATHS>(vb);
            float2 fa = __half22float2(sa);
            float2 fbv = __half22float2(sb);
            acc1.x = fmaf(fa.x,  w1.x, acc1.x);
            acc1.y = fmaf(fa.y,  w1.y, acc1.y);
            acc1.z = fmaf(fbv.x, w1.z, acc1.z);
            acc1.w = fmaf(fbv.y, w1.w, acc1.w);
        }
    }
}

__global__ void __launch_bounds__(256, 4)
gather_kernel(const int* __restrict__ paths, const int* __restrict__ ptypes,
              int feats_sel, int layer)
{
    const uint2* __restrict__ feats2 = (const uint2*)buf_ptr(feats_sel);
    const float4* __restrict__ wres4 =
        (const float4*)(g_wres + (size_t)layer * N_TYPES * PATH_LEN * HID);

    __shared__ int off_s[8][N_PATHS * PATH_LEN];   // [slot][l*8 + pos]
    __shared__ int types_s[N_PATHS];

    const int tid  = threadIdx.x;
    const int slot = tid >> 5;
    const int lane = tid & 31;
    const int n    = blockIdx.x * 8 + slot;

    if (tid < N_PATHS) types_s[tid] = ptypes[tid];
    __syncthreads();

    unsigned tmask = 0;
#pragma unroll
    for (int p = 0; p < N_PATHS; p++)
        tmask |= (types_s[p] ? 1u : 0u) << p;
    const int c0 = N_PATHS - __popc(tmask);

    {
        int i  = tid * 2;
        int sl = i >> 6;
        int r  = i & 63;
        int p  = r >> 3, l = r & 7;
        int nn = blockIdx.x * 8 + sl;
        int2 v = *(const int2*)(paths + (size_t)p * (N_NODES * PATH_LEN)
                                + (size_t)nn * PATH_LEN + l);
        unsigned below = (1u << p) - 1u;
        int pos = (tmask >> p) & 1
                ? c0 + __popc(tmask & below)
                : __popc(~tmask & below & 0xFFu);
        off_s[sl][l * N_PATHS + pos]       = v.x * (HID / 4);
        off_s[sl][(l + 1) * N_PATHS + pos] = v.y * (HID / 4);
    }
    __syncthreads();

    const uint2* fb = feats2 + lane;
    const int* orow = off_s[slot];

    float4 acc0 = make_float4(0.f, 0.f, 0.f, 0.f);
    float4 acc1 = make_float4(0.f, 0.f, 0.f, 0.f);

    switch (c0) {
        case 0: gather_core<0>(fb, orow, wres4, lane, acc0, acc1); break;
        case 1: gather_core<1>(fb, orow, wres4, lane, acc0, acc1); break;
        case 2: gather_core<2>(fb, orow, wres4, lane, acc0, acc1); break;
        case 3: gather_core<3>(fb, orow, wres4, lane, acc0, acc1); break;
        case 4: gather_core<4>(fb, orow, wres4, lane, acc0, acc1); break;
        case 5: gather_core<5>(fb, orow, wres4, lane, acc0, acc1); break;
        case 6: gather_core<6>(fb, orow, wres4, lane, acc0, acc1); break;
        case 7: gather_core<7>(fb, orow, wres4, lane, acc0, acc1); break;
        default: gather_core<8>(fb, orow, wres4, lane, acc0, acc1); break;
    }

    // store fout as fp16: node row = 256 halves = 64 uint2
    uint2* fo = (uint2*)(g_fout + (size_t)n * (N_TYPES * HID));
    __half2 a01 = __floats2half2_rn(acc0.x, acc0.y);
    __half2 a23 = __floats2half2_rn(acc0.z, acc0.w);
    __half2 b01 = __floats2half2_rn(acc1.x, acc1.y);
    __half2 b23 = __floats2half2_rn(acc1.z, acc1.w);
    fo[lane]      = make_uint2(*(uint32_t*)&a01, *(uint32_t*)&a23);
    fo[32 + lane] = make_uint2(*(uint32_t*)&b01, *(uint32_t*)&b23);
}

// ============================================================================
extern "C" void kernel_launch(void* const* d_in, const int* in_sizes, int n_in,
                              void* d_out, int out_size)
{
    const float* input_x    = (const float*)d_in[0];
    const int*   paths      = (const int*)d_in[1];
    const int*   ptypes     = (const int*)d_in[2];
    const float* fc_in_w    = (const float*)d_in[3];
    const float* fc_in_b    = (const float*)d_in[4];
    const float* fc_out_w   = (const float*)d_in[5];
    const float* fc_out_b   = (const float*)d_in[6];
    const float* layer_fc_w = (const float*)d_in[7];
    const float* path_w     = (const float*)d_in[8];
    float* out = (float*)d_out;

    constexpr int LDSH = 40, NST = 3;
    constexpr size_t SM_128 = (size_t)NST * (64 * LDSH + 128 * LDSH) * 2; // 46080
    constexpr size_t SM_64  = (size_t)NST * (64 * LDSH + 64 * LDSH) * 2;  // 30720

    __half *in_feats_p, *bufA_p, *bufB_p, *fout_p, *x_h_p;
    __half *w_in_p, *w_layer_p, *w_out_p;
    cudaGetSymbolAddress((void**)&in_feats_p, g_in_feats);
    cudaGetSymbolAddress((void**)&bufA_p, g_bufA);
    cudaGetSymbolAddress((void**)&bufB_p, g_bufB);
    cudaGetSymbolAddress((void**)&fout_p, g_fout);
    cudaGetSymbolAddress((void**)&x_h_p, g_x_h);
    cudaGetSymbolAddress((void**)&w_in_p, g_w_in);
    cudaGetSymbolAddress((void**)&w_layer_p, g_w_layer);
    cudaGetSymbolAddress((void**)&w_out_p, g_w_out);

    const dim3 blk(256);
    const dim3 ggrd((N_NODES + 63) / 64);

    resolve_all_w_kernel<<<(N_LAYERS * N_TYPES * PATH_LEN * HID + 255) / 256,
                           blk>>>(path_w, ptypes);
    convert_all_kernel<<<(N_NODES * IN_DIM + 255) / 256, blk>>>(
        input_x, fc_in_w, layer_fc_w, fc_out_w);

    gemm_h_kernel<IN_DIM, HID, 0, true><<<ggrd, blk, SM_128>>>(
        x_h_p, w_in_p, fc_in_b, nullptr, nullptr, in_feats_p);

    int cur = 0;  // feats = g_in_feats
    __half* bufs[3] = {in_feats_p, bufA_p, bufB_p};
    for (int i = 0; i < N_LAYERS; i++) {
        gather_kernel<<<N_NODES / 8, blk>>>(paths, ptypes, cur, i);
        int nxt = (cur == 1) ? 2 : 1;
        gemm_h_kernel<N_TYPES * HID, HID, 1, true><<<ggrd, blk, SM_128>>>(
            fout_p, w_layer_p + (size_t)i * HID * (N_TYPES * HID), nullptr,
            bufs[cur], in_feats_p, bufs[nxt]);
        cur = nxt;
    }

    gemm_h_kernel<HID, OUT_DIM, 0, false><<<ggrd, blk, SM_64>>>(
        bufs[cur], w_out_p, fc_out_b, nullptr, nullptr, out);
}